// round 1
// baseline (speedup 1.0000x reference)
#include <cuda_runtime.h>
#include <math.h>

#define SDIM 1024
#define DDIM 1024
#define BATCH 4
#define NH 16
#define HD 64
#define NBH 64      // BATCH*NH
#define MTOT 4096   // BATCH*SDIM

// Scratch: __device__ globals (sanctioned — no runtime allocation allowed)
__device__ float g_qh[NBH * SDIM * HD];                       // 16 MB, [bh][s][hd]
__device__ float g_kh[NBH * SDIM * HD];                       // 16 MB
__device__ float g_vh[NBH * SDIM * HD];                       // 16 MB
__device__ float g_sc[(size_t)NBH * SDIM * SDIM];             // 256 MB, [bh][q][k]
__device__ float g_attn[(size_t)MTOT * DDIM];                 // 16 MB, [b*s][d]

// ---------------------------------------------------------------------------
// FP32 SGEMM: C[M=4096, N=1024] = A[4096,1024] @ W[1024,1024] + bias
// 128x128 block tile, BK=16, 256 threads, 8x8 per-thread register tile.
// head_layout=1: scatter output to [bh][s][hd]; else plain row-major.
// ---------------------------------------------------------------------------
__global__ __launch_bounds__(256, 2)
void gemm_kernel(const float* __restrict__ A, const float* __restrict__ W,
                 const float* __restrict__ bias, float* __restrict__ out,
                 int head_layout)
{
    __shared__ float As[16][128];
    __shared__ float Ws[16][128];
    const int tid = threadIdx.x;
    const int tx = tid & 15;
    const int ty = tid >> 4;
    const int row0 = blockIdx.y << 7;
    const int col0 = blockIdx.x << 7;

    float acc[8][8];
#pragma unroll
    for (int i = 0; i < 8; i++)
#pragma unroll
        for (int j = 0; j < 8; j++) acc[i][j] = 0.f;

    for (int kc = 0; kc < 1024; kc += 16) {
#pragma unroll
        for (int i = 0; i < 2; i++) {
            int l = i * 256 + tid;
            int ar = l >> 2, ac = (l & 3) << 2;
            float4 va = *(const float4*)(A + (size_t)(row0 + ar) * 1024 + kc + ac);
            As[ac + 0][ar] = va.x;
            As[ac + 1][ar] = va.y;
            As[ac + 2][ar] = va.z;
            As[ac + 3][ar] = va.w;
            int wr = l >> 5, wc = (l & 31) << 2;
            *(float4*)&Ws[wr][wc] = *(const float4*)(W + (size_t)(kc + wr) * 1024 + col0 + wc);
        }
        __syncthreads();
#pragma unroll
        for (int k = 0; k < 16; k++) {
            float a[8], b[8];
            *(float4*)&a[0] = *(const float4*)&As[k][ty << 2];
            *(float4*)&a[4] = *(const float4*)&As[k][64 + (ty << 2)];
            *(float4*)&b[0] = *(const float4*)&Ws[k][tx << 2];
            *(float4*)&b[4] = *(const float4*)&Ws[k][64 + (tx << 2)];
#pragma unroll
            for (int i = 0; i < 8; i++)
#pragma unroll
                for (int j = 0; j < 8; j++)
                    acc[i][j] += a[i] * b[j];
        }
        __syncthreads();
    }

#pragma unroll
    for (int i = 0; i < 8; i++) {
        int r = row0 + ((i < 4) ? ((ty << 2) + i) : (64 + (ty << 2) + (i - 4)));
#pragma unroll
        for (int jj = 0; jj < 2; jj++) {
            int c = col0 + jj * 64 + (tx << 2);
            float4 v;
            v.x = acc[i][jj * 4 + 0] + bias[c + 0];
            v.y = acc[i][jj * 4 + 1] + bias[c + 1];
            v.z = acc[i][jj * 4 + 2] + bias[c + 2];
            v.w = acc[i][jj * 4 + 3] + bias[c + 3];
            if (head_layout) {
                int b_ = r >> 10, s_ = r & 1023;
                int h_ = c >> 6, d_ = c & 63;
                *(float4*)(out + ((size_t)((b_ * NH + h_) * SDIM + s_)) * HD + d_) = v;
            } else {
                *(float4*)(out + (size_t)r * 1024 + c) = v;
            }
        }
    }
}

// ---------------------------------------------------------------------------
// Scores: per (b,h): S[q][k] = (1/8) * sum_d q[q][d]*k[k][d].  K-dim = 64.
// Same 128x128x16 structure; both operands transposed on load.
// ---------------------------------------------------------------------------
__global__ __launch_bounds__(256, 2)
void scores_kernel(const float* __restrict__ qh, const float* __restrict__ kh,
                   float* __restrict__ sc)
{
    const int bh = blockIdx.z;
    const float* A = qh + (size_t)bh * SDIM * HD;
    const float* B = kh + (size_t)bh * SDIM * HD;
    float* out = sc + (size_t)bh * SDIM * SDIM;

    __shared__ float As[16][128];
    __shared__ float Bs[16][128];
    const int tid = threadIdx.x;
    const int tx = tid & 15;
    const int ty = tid >> 4;
    const int row0 = blockIdx.y << 7;   // query tile
    const int col0 = blockIdx.x << 7;   // key tile

    float acc[8][8];
#pragma unroll
    for (int i = 0; i < 8; i++)
#pragma unroll
        for (int j = 0; j < 8; j++) acc[i][j] = 0.f;

#pragma unroll
    for (int kc = 0; kc < 64; kc += 16) {
#pragma unroll
        for (int i = 0; i < 2; i++) {
            int l = i * 256 + tid;
            int ar = l >> 2, ac = (l & 3) << 2;
            float4 va = *(const float4*)(A + (size_t)(row0 + ar) * HD + kc + ac);
            As[ac + 0][ar] = va.x;
            As[ac + 1][ar] = va.y;
            As[ac + 2][ar] = va.z;
            As[ac + 3][ar] = va.w;
            float4 vb = *(const float4*)(B + (size_t)(col0 + ar) * HD + kc + ac);
            Bs[ac + 0][ar] = vb.x;
            Bs[ac + 1][ar] = vb.y;
            Bs[ac + 2][ar] = vb.z;
            Bs[ac + 3][ar] = vb.w;
        }
        __syncthreads();
#pragma unroll
        for (int k = 0; k < 16; k++) {
            float a[8], b[8];
            *(float4*)&a[0] = *(const float4*)&As[k][ty << 2];
            *(float4*)&a[4] = *(const float4*)&As[k][64 + (ty << 2)];
            *(float4*)&b[0] = *(const float4*)&Bs[k][tx << 2];
            *(float4*)&b[4] = *(const float4*)&Bs[k][64 + (tx << 2)];
#pragma unroll
            for (int i = 0; i < 8; i++)
#pragma unroll
                for (int j = 0; j < 8; j++)
                    acc[i][j] += a[i] * b[j];
        }
        __syncthreads();
    }

#pragma unroll
    for (int i = 0; i < 8; i++) {
        int r = row0 + ((i < 4) ? ((ty << 2) + i) : (64 + (ty << 2) + (i - 4)));
#pragma unroll
        for (int jj = 0; jj < 2; jj++) {
            int c = col0 + jj * 64 + (tx << 2);
            float4 v;
            v.x = acc[i][jj * 4 + 0] * 0.125f;
            v.y = acc[i][jj * 4 + 1] * 0.125f;
            v.z = acc[i][jj * 4 + 2] * 0.125f;
            v.w = acc[i][jj * 4 + 3] * 0.125f;
            *(float4*)(out + (size_t)r * SDIM + c) = v;
        }
    }
}

// ---------------------------------------------------------------------------
// Mask + second softmax + sparse AV.
// Block = 8 query rows of one (b,h). Warp per query. Survivors (att >= 0.019)
// are ballot-compacted into a list (typ. 1-3 entries), then out = sum w_k*v_k.
// ---------------------------------------------------------------------------
__global__ __launch_bounds__(256)
void mask_av_kernel(const float* __restrict__ sc, const float* __restrict__ vh,
                    float* __restrict__ attn)
{
    __shared__ float rows[8][1024];   // 32 KB
    __shared__ int   listK[8][64];
    __shared__ float listW[8][64];

    const int bh = blockIdx.y;
    const int q0 = blockIdx.x << 3;
    const int tid = threadIdx.x;

    const float* src = sc + ((size_t)bh * SDIM + q0) * SDIM;
    for (int i = tid; i < 8 * 1024 / 4; i += 256)
        *(float4*)&rows[0][i * 4] = *(const float4*)&src[(size_t)i * 4];
    __syncthreads();

    const int qi = tid >> 5;
    const int lane = tid & 31;
    const float* row = rows[qi];

    // row max
    float m = -3.4e38f;
    for (int k = lane; k < 1024; k += 32) m = fmaxf(m, row[k]);
#pragma unroll
    for (int o = 16; o > 0; o >>= 1) m = fmaxf(m, __shfl_xor_sync(0xffffffffu, m, o));

    // Z of temperature softmax (TEMP = 0.001, mimic reference: divide)
    const float mp = m / 0.001f;
    float zl = 0.f;
    for (int k = lane; k < 1024; k += 32) zl += expf(row[k] / 0.001f - mp);
#pragma unroll
    for (int o = 16; o > 0; o >>= 1) zl += __shfl_xor_sync(0xffffffffu, zl, o);
    const float Z = zl;

    // survivors: att = exp((s-m)/T)/Z >= 0.019
    int cnt = 0;
    float m2 = -3.4e38f;
    for (int it = 0; it < 32; it++) {
        int k = it * 32 + lane;
        float s = row[k];
        float att = expf(s / 0.001f - mp) / Z;
        bool surv = (att >= 0.019f);
        unsigned bm = __ballot_sync(0xffffffffu, surv);
        if (surv) {
            int pos = cnt + __popc(bm & ((1u << lane) - 1u));
            if (pos < 64) listK[qi][pos] = k;
            m2 = fmaxf(m2, s);
        }
        cnt += __popc(bm);
    }
#pragma unroll
    for (int o = 16; o > 0; o >>= 1) m2 = fmaxf(m2, __shfl_xor_sync(0xffffffffu, m2, o));
    __syncwarp();

    // second softmax normalizer over survivors (masked entries underflow to 0)
    float sum2 = 0.f;
    const bool normal = (cnt >= 1 && cnt <= 64);
    if (normal) {
        float sl = 0.f;
        for (int j = lane; j < cnt; j += 32) {
            float e = expf(row[listK[qi][j]] - m2);
            listW[qi][j] = e;
            sl += e;
        }
#pragma unroll
        for (int o = 16; o > 0; o >>= 1) sl += __shfl_xor_sync(0xffffffffu, sl, o);
        sum2 = sl;
    } else if (cnt > 64) {
        float sl = 0.f;
        for (int k = lane; k < 1024; k += 32) {
            float s = row[k];
            float att = expf(s / 0.001f - mp) / Z;
            if (att >= 0.019f) sl += expf(s - m2);
        }
#pragma unroll
        for (int o = 16; o > 0; o >>= 1) sl += __shfl_xor_sync(0xffffffffu, sl, o);
        sum2 = sl;
    }
    __syncwarp();

    // sparse AV: lane handles dims (lane, lane+32)
    const float* vb = vh + (size_t)bh * SDIM * HD;
    float a0 = 0.f, a1 = 0.f;
    if (normal) {
        for (int j = 0; j < cnt; j++) {
            int k = listK[qi][j];
            float w = listW[qi][j] / sum2;
            a0 += w * vb[(size_t)k * HD + lane];
            a1 += w * vb[(size_t)k * HD + lane + 32];
        }
    } else {
        // cnt==0: all rows masked -> uniform softmax over all 1024 keys.
        // cnt>64: overflow -> full rescan.
        for (int k = 0; k < 1024; k++) {
            float w;
            if (cnt == 0) {
                w = 1.0f / 1024.0f;
            } else {
                float s = row[k];
                float att = expf(s / 0.001f - mp) / Z;
                w = (att >= 0.019f) ? (expf(s - m2) / sum2) : 0.f;
            }
            a0 += w * vb[(size_t)k * HD + lane];
            a1 += w * vb[(size_t)k * HD + lane + 32];
        }
    }

    const int b_ = bh >> 4, h_ = bh & 15;
    const int q = q0 + qi;
    float* dst = attn + ((size_t)(b_ * SDIM + q)) * DDIM + h_ * HD;
    dst[lane] = a0;
    dst[lane + 32] = a1;
}

// ---------------------------------------------------------------------------
extern "C" void kernel_launch(void* const* d_in, const int* in_sizes, int n_in,
                              void* d_out, int out_size)
{
    const float* Q  = (const float*)d_in[0];
    const float* K  = (const float*)d_in[1];
    const float* V  = (const float*)d_in[2];
    const float* Wq = (const float*)d_in[3];
    const float* bq = (const float*)d_in[4];
    const float* Wk = (const float*)d_in[5];
    const float* bk = (const float*)d_in[6];
    const float* Wv = (const float*)d_in[7];
    const float* bv = (const float*)d_in[8];
    const float* Wo = (const float*)d_in[9];
    const float* bo = (const float*)d_in[10];

    float *qh, *kh, *vh, *scr, *attn;
    cudaGetSymbolAddress((void**)&qh,   g_qh);
    cudaGetSymbolAddress((void**)&kh,   g_kh);
    cudaGetSymbolAddress((void**)&vh,   g_vh);
    cudaGetSymbolAddress((void**)&scr,  g_sc);
    cudaGetSymbolAddress((void**)&attn, g_attn);

    dim3 gproj(DDIM / 128, MTOT / 128);          // (8, 32)
    gemm_kernel<<<gproj, 256>>>(Q, Wq, bq, qh, 1);
    gemm_kernel<<<gproj, 256>>>(K, Wk, bk, kh, 1);
    gemm_kernel<<<gproj, 256>>>(V, Wv, bv, vh, 1);

    dim3 gsc(SDIM / 128, SDIM / 128, NBH);       // (8, 8, 64)
    scores_kernel<<<gsc, 256>>>(qh, kh, scr);

    dim3 gmask(SDIM / 8, NBH);                   // (128, 64)
    mask_av_kernel<<<gmask, 256>>>(scr, vh, attn);

    gemm_kernel<<<gproj, 256>>>(attn, Wo, bo, (float*)d_out, 0);
}

// round 2
// speedup vs baseline: 1.0455x; 1.0455x over previous
#include <cuda_runtime.h>
#include <math.h>

#define SDIM 1024
#define DDIM 1024
#define BATCH 4
#define NH 16
#define HD 64
#define NBH 64      // BATCH*NH
#define MTOT 4096   // BATCH*SDIM

// Scratch: __device__ globals (no runtime allocation allowed)
__device__ float g_qh[NBH * SDIM * HD];                       // 16 MB, [bh][s][hd]
__device__ float g_kh[NBH * SDIM * HD];                       // 16 MB
__device__ float g_vh[NBH * SDIM * HD];                       // 16 MB
__device__ float g_sc[(size_t)NBH * SDIM * SDIM];             // 256 MB, [bh][q][k]
__device__ float g_attn[(size_t)MTOT * DDIM];                 // 16 MB, [b*s][d]

// Packed fp32x2 helpers (Blackwell FFMA2 — ptxas never emits this from C++)
#define PACK2(d, lo, hi) \
    asm("mov.b64 %0, {%1, %2};" : "=l"(d) : "f"(lo), "f"(hi))
#define FMA2(acc, a, b) \
    asm("fma.rn.f32x2 %0, %1, %2, %0;" : "+l"(acc) : "l"(a), "l"(b))
#define UNPACK2(lo, hi, v) \
    asm("mov.b64 {%0, %1}, %2;" : "=f"(lo), "=f"(hi) : "l"(v))

// ---------------------------------------------------------------------------
// FP32 SGEMM via FFMA2: C[4096,1024] = A[4096,1024] @ W[1024,1024] + bias
// 128x128 block tile, BK=16, 256 threads, 8x8 per-thread tile (packed 8x4 f32x2)
// ---------------------------------------------------------------------------
__global__ __launch_bounds__(256, 2)
void gemm_kernel(const float* __restrict__ A, const float* __restrict__ W,
                 const float* __restrict__ bias, float* __restrict__ out,
                 int head_layout)
{
    __shared__ __align__(16) float As[16][128];
    __shared__ __align__(16) float Ws[16][128];
    const int tid = threadIdx.x;
    const int tx = tid & 15;
    const int ty = tid >> 4;
    const int row0 = blockIdx.y << 7;
    const int col0 = blockIdx.x << 7;

    unsigned long long acc2[8][4];
#pragma unroll
    for (int i = 0; i < 8; i++)
#pragma unroll
        for (int j = 0; j < 4; j++) acc2[i][j] = 0ull;

    for (int kc = 0; kc < 1024; kc += 16) {
#pragma unroll
        for (int i = 0; i < 2; i++) {
            int l = i * 256 + tid;
            int ar = l >> 2, ac = (l & 3) << 2;
            float4 va = *(const float4*)(A + (size_t)(row0 + ar) * 1024 + kc + ac);
            As[ac + 0][ar] = va.x;
            As[ac + 1][ar] = va.y;
            As[ac + 2][ar] = va.z;
            As[ac + 3][ar] = va.w;
            int wr = l >> 5, wc = (l & 31) << 2;
            *(float4*)&Ws[wr][wc] = *(const float4*)(W + (size_t)(kc + wr) * 1024 + col0 + wc);
        }
        __syncthreads();
#pragma unroll
        for (int k = 0; k < 16; k++) {
            float a[8];
            *(float4*)&a[0] = *(const float4*)&As[k][ty << 2];
            *(float4*)&a[4] = *(const float4*)&As[k][64 + (ty << 2)];
            ulonglong2 t0 = *(const ulonglong2*)&Ws[k][tx << 2];
            ulonglong2 t1 = *(const ulonglong2*)&Ws[k][64 + (tx << 2)];
#pragma unroll
            for (int i = 0; i < 8; i++) {
                unsigned long long ad;
                PACK2(ad, a[i], a[i]);
                FMA2(acc2[i][0], ad, t0.x);
                FMA2(acc2[i][1], ad, t0.y);
                FMA2(acc2[i][2], ad, t1.x);
                FMA2(acc2[i][3], ad, t1.y);
            }
        }
        __syncthreads();
    }

#pragma unroll
    for (int i = 0; i < 8; i++) {
        int r = row0 + ((i < 4) ? ((ty << 2) + i) : (64 + (ty << 2) + (i - 4)));
#pragma unroll
        for (int jj = 0; jj < 2; jj++) {
            int c = col0 + jj * 64 + (tx << 2);
            float4 v;
            UNPACK2(v.x, v.y, acc2[i][jj * 2 + 0]);
            UNPACK2(v.z, v.w, acc2[i][jj * 2 + 1]);
            v.x += bias[c + 0];
            v.y += bias[c + 1];
            v.z += bias[c + 2];
            v.w += bias[c + 3];
            if (head_layout) {
                int b_ = r >> 10, s_ = r & 1023;
                int h_ = c >> 6, d_ = c & 63;
                *(float4*)(out + ((size_t)((b_ * NH + h_) * SDIM + s_)) * HD + d_) = v;
            } else {
                *(float4*)(out + (size_t)r * 1024 + c) = v;
            }
        }
    }
}

// ---------------------------------------------------------------------------
// Scores via FFMA2: per (b,h): S[q][k] = (1/8) * sum_d q[q][d]*k[k][d]
// ---------------------------------------------------------------------------
__global__ __launch_bounds__(256, 2)
void scores_kernel(const float* __restrict__ qh, const float* __restrict__ kh,
                   float* __restrict__ sc)
{
    const int bh = blockIdx.z;
    const float* A = qh + (size_t)bh * SDIM * HD;
    const float* B = kh + (size_t)bh * SDIM * HD;
    float* out = sc + (size_t)bh * SDIM * SDIM;

    __shared__ __align__(16) float As[16][128];
    __shared__ __align__(16) float Bs[16][128];
    const int tid = threadIdx.x;
    const int tx = tid & 15;
    const int ty = tid >> 4;
    const int row0 = blockIdx.y << 7;
    const int col0 = blockIdx.x << 7;

    unsigned long long acc2[8][4];
#pragma unroll
    for (int i = 0; i < 8; i++)
#pragma unroll
        for (int j = 0; j < 4; j++) acc2[i][j] = 0ull;

#pragma unroll
    for (int kc = 0; kc < 64; kc += 16) {
#pragma unroll
        for (int i = 0; i < 2; i++) {
            int l = i * 256 + tid;
            int ar = l >> 2, ac = (l & 3) << 2;
            float4 va = *(const float4*)(A + (size_t)(row0 + ar) * HD + kc + ac);
            As[ac + 0][ar] = va.x;
            As[ac + 1][ar] = va.y;
            As[ac + 2][ar] = va.z;
            As[ac + 3][ar] = va.w;
            float4 vb = *(const float4*)(B + (size_t)(col0 + ar) * HD + kc + ac);
            Bs[ac + 0][ar] = vb.x;
            Bs[ac + 1][ar] = vb.y;
            Bs[ac + 2][ar] = vb.z;
            Bs[ac + 3][ar] = vb.w;
        }
        __syncthreads();
#pragma unroll
        for (int k = 0; k < 16; k++) {
            float a[8];
            *(float4*)&a[0] = *(const float4*)&As[k][ty << 2];
            *(float4*)&a[4] = *(const float4*)&As[k][64 + (ty << 2)];
            ulonglong2 t0 = *(const ulonglong2*)&Bs[k][tx << 2];
            ulonglong2 t1 = *(const ulonglong2*)&Bs[k][64 + (tx << 2)];
#pragma unroll
            for (int i = 0; i < 8; i++) {
                unsigned long long ad;
                PACK2(ad, a[i], a[i]);
                FMA2(acc2[i][0], ad, t0.x);
                FMA2(acc2[i][1], ad, t0.y);
                FMA2(acc2[i][2], ad, t1.x);
                FMA2(acc2[i][3], ad, t1.y);
            }
        }
        __syncthreads();
    }

#pragma unroll
    for (int i = 0; i < 8; i++) {
        int r = row0 + ((i < 4) ? ((ty << 2) + i) : (64 + (ty << 2) + (i - 4)));
#pragma unroll
        for (int jj = 0; jj < 2; jj++) {
            int c = col0 + jj * 64 + (tx << 2);
            float4 v;
            UNPACK2(v.x, v.y, acc2[i][jj * 2 + 0]);
            UNPACK2(v.z, v.w, acc2[i][jj * 2 + 1]);
            v.x *= 0.125f;
            v.y *= 0.125f;
            v.z *= 0.125f;
            v.w *= 0.125f;
            *(float4*)(out + (size_t)r * SDIM + c) = v;
        }
    }
}

// ---------------------------------------------------------------------------
// Mask + second softmax + sparse AV (unchanged from R1 — proven exact).
// Block = 8 query rows of one (b,h). Warp per query.
// ---------------------------------------------------------------------------
__global__ __launch_bounds__(256)
void mask_av_kernel(const float* __restrict__ sc, const float* __restrict__ vh,
                    float* __restrict__ attn)
{
    __shared__ float rows[8][1024];   // 32 KB
    __shared__ int   listK[8][64];
    __shared__ float listW[8][64];

    const int bh = blockIdx.y;
    const int q0 = blockIdx.x << 3;
    const int tid = threadIdx.x;

    const float* src = sc + ((size_t)bh * SDIM + q0) * SDIM;
    for (int i = tid; i < 8 * 1024 / 4; i += 256)
        *(float4*)&rows[0][i * 4] = *(const float4*)&src[(size_t)i * 4];
    __syncthreads();

    const int qi = tid >> 5;
    const int lane = tid & 31;
    const float* row = rows[qi];

    // row max
    float m = -3.4e38f;
    for (int k = lane; k < 1024; k += 32) m = fmaxf(m, row[k]);
#pragma unroll
    for (int o = 16; o > 0; o >>= 1) m = fmaxf(m, __shfl_xor_sync(0xffffffffu, m, o));

    // Z of temperature softmax (TEMP = 0.001)
    const float mp = m / 0.001f;
    float zl = 0.f;
    for (int k = lane; k < 1024; k += 32) zl += expf(row[k] / 0.001f - mp);
#pragma unroll
    for (int o = 16; o > 0; o >>= 1) zl += __shfl_xor_sync(0xffffffffu, zl, o);
    const float Z = zl;

    // survivors: att = exp((s-m)/T)/Z >= 0.019
    int cnt = 0;
    float m2 = -3.4e38f;
    for (int it = 0; it < 32; it++) {
        int k = it * 32 + lane;
        float s = row[k];
        float att = expf(s / 0.001f - mp) / Z;
        bool surv = (att >= 0.019f);
        unsigned bm = __ballot_sync(0xffffffffu, surv);
        if (surv) {
            int pos = cnt + __popc(bm & ((1u << lane) - 1u));
            if (pos < 64) listK[qi][pos] = k;
            m2 = fmaxf(m2, s);
        }
        cnt += __popc(bm);
    }
#pragma unroll
    for (int o = 16; o > 0; o >>= 1) m2 = fmaxf(m2, __shfl_xor_sync(0xffffffffu, m2, o));
    __syncwarp();

    float sum2 = 0.f;
    const bool normal = (cnt >= 1 && cnt <= 64);
    if (normal) {
        float sl = 0.f;
        for (int j = lane; j < cnt; j += 32) {
            float e = expf(row[listK[qi][j]] - m2);
            listW[qi][j] = e;
            sl += e;
        }
#pragma unroll
        for (int o = 16; o > 0; o >>= 1) sl += __shfl_xor_sync(0xffffffffu, sl, o);
        sum2 = sl;
    } else if (cnt > 64) {
        float sl = 0.f;
        for (int k = lane; k < 1024; k += 32) {
            float s = row[k];
            float att = expf(s / 0.001f - mp) / Z;
            if (att >= 0.019f) sl += expf(s - m2);
        }
#pragma unroll
        for (int o = 16; o > 0; o >>= 1) sl += __shfl_xor_sync(0xffffffffu, sl, o);
        sum2 = sl;
    }
    __syncwarp();

    // sparse AV: lane handles dims (lane, lane+32)
    const float* vb = vh + (size_t)bh * SDIM * HD;
    float a0 = 0.f, a1 = 0.f;
    if (normal) {
        for (int j = 0; j < cnt; j++) {
            int k = listK[qi][j];
            float w = listW[qi][j] / sum2;
            a0 += w * vb[(size_t)k * HD + lane];
            a1 += w * vb[(size_t)k * HD + lane + 32];
        }
    } else {
        for (int k = 0; k < 1024; k++) {
            float w;
            if (cnt == 0) {
                w = 1.0f / 1024.0f;
            } else {
                float s = row[k];
                float att = expf(s / 0.001f - mp) / Z;
                w = (att >= 0.019f) ? (expf(s - m2) / sum2) : 0.f;
            }
            a0 += w * vb[(size_t)k * HD + lane];
            a1 += w * vb[(size_t)k * HD + lane + 32];
        }
    }

    const int b_ = bh >> 4, h_ = bh & 15;
    const int q = q0 + qi;
    float* dst = attn + ((size_t)(b_ * SDIM + q)) * DDIM + h_ * HD;
    dst[lane] = a0;
    dst[lane + 32] = a1;
}

// ---------------------------------------------------------------------------
extern "C" void kernel_launch(void* const* d_in, const int* in_sizes, int n_in,
                              void* d_out, int out_size)
{
    const float* Q  = (const float*)d_in[0];
    const float* K  = (const float*)d_in[1];
    const float* V  = (const float*)d_in[2];
    const float* Wq = (const float*)d_in[3];
    const float* bq = (const float*)d_in[4];
    const float* Wk = (const float*)d_in[5];
    const float* bk = (const float*)d_in[6];
    const float* Wv = (const float*)d_in[7];
    const float* bv = (const float*)d_in[8];
    const float* Wo = (const float*)d_in[9];
    const float* bo = (const float*)d_in[10];

    float *qh, *kh, *vh, *scr, *attn;
    cudaGetSymbolAddress((void**)&qh,   g_qh);
    cudaGetSymbolAddress((void**)&kh,   g_kh);
    cudaGetSymbolAddress((void**)&vh,   g_vh);
    cudaGetSymbolAddress((void**)&scr,  g_sc);
    cudaGetSymbolAddress((void**)&attn, g_attn);

    dim3 gproj(DDIM / 128, MTOT / 128);          // (8, 32)
    gemm_kernel<<<gproj, 256>>>(Q, Wq, bq, qh, 1);
    gemm_kernel<<<gproj, 256>>>(K, Wk, bk, kh, 1);
    gemm_kernel<<<gproj, 256>>>(V, Wv, bv, vh, 1);

    dim3 gsc(SDIM / 128, SDIM / 128, NBH);       // (8, 8, 64)
    scores_kernel<<<gsc, 256>>>(qh, kh, scr);

    dim3 gmask(SDIM / 8, NBH);                   // (128, 64)
    mask_av_kernel<<<gmask, 256>>>(scr, vh, attn);

    gemm_kernel<<<gproj, 256>>>(attn, Wo, bo, (float*)d_out, 0);
}

// round 4
// speedup vs baseline: 1.0735x; 1.0268x over previous
#include <cuda_runtime.h>
#include <math.h>
#include <stdint.h>
#include <float.h>

#define SDIM 1024
#define DDIM 1024
#define NH 16
#define HD 64
#define NBH 64
#define MTOT 4096

// ---------------- scratch (__device__ globals; no runtime alloc) ------------
__device__ float g_qh[NBH * SDIM * HD];
__device__ float g_kh[NBH * SDIM * HD];
__device__ float g_vh[NBH * SDIM * HD];
__device__ float g_sc[(size_t)NBH * SDIM * SDIM];   // 256 MB
__device__ float g_attn[(size_t)MTOT * DDIM];
__device__ float g_wvT[DDIM * DDIM];
__device__ float g_woT[DDIM * DDIM];

// ---------------- helpers ----------------------------------------------------
__device__ __forceinline__ float to_tf32(float x) {
    uint32_t u;
    asm("cvt.rna.tf32.f32 %0, %1;" : "=r"(u) : "f"(x));
    return __uint_as_float(u);
}

#define MMA_TF32(d, a, b) \
    asm volatile("mma.sync.aligned.m16n8k8.row.col.f32.tf32.tf32.f32 " \
                 "{%0,%1,%2,%3}, {%4,%5,%6,%7}, {%8,%9}, {%0,%1,%2,%3};" \
                 : "+f"((d)[0]), "+f"((d)[1]), "+f"((d)[2]), "+f"((d)[3]) \
                 : "r"((a)[0]), "r"((a)[1]), "r"((a)[2]), "r"((a)[3]), \
                   "r"((b)[0]), "r"((b)[1]))

// plane stride: 36 floats/row -> frag-load banks (4g+t) conflict-free
#define PLD 36
#define PLANE (128 * PLD)

// ---------------------------------------------------------------------------
// Tensor-pipe GEMM via mma.sync tf32.
// C[m,n] = scale * sum_k A[m,k]*B[n,k] + bias[n]
// A row-major [M, lda], B row-major [N, ldb] (pre-transposed weights).
// 128x128 block tile, BK=32 chunks. NPASS=3: tf32 split (hh+hl+lh), ~fp32 acc.
// NPASS=1: plain tf32 (scores path — mask fixup absorbs the noise).
// ---------------------------------------------------------------------------
template <int NPASS>
__global__ __launch_bounds__(256, 1)
void mma_gemm(const float* __restrict__ Abase, size_t sA, int lda,
              const float* __restrict__ Bbase, size_t sB, int ldb,
              const float* __restrict__ bias,
              float* __restrict__ Cbase, size_t sC,
              int nchunks, float scale, int head_layout)
{
    extern __shared__ __align__(16) float smf[];
    float* Ah = smf;
    float* Bh = smf + PLANE;
    float* Al = smf + 2 * PLANE;   // only used when NPASS==3
    float* Bl = smf + 3 * PLANE;

    const int tid = threadIdx.x;
    const int w = tid >> 5;
    const int lane = tid & 31;
    const int g = lane >> 2;
    const int t = lane & 3;
    const int m0 = (w & 1) << 6;       // warp m offset within block tile
    const int n0 = (w >> 1) << 5;      // warp n offset

    const float* A = Abase + (size_t)blockIdx.z * sA;
    const float* B = Bbase + (size_t)blockIdx.z * sB;
    float* C = Cbase + (size_t)blockIdx.z * sC;
    const int row0 = blockIdx.y << 7;
    const int col0 = blockIdx.x << 7;

    float d[4][4][4];
#pragma unroll
    for (int i = 0; i < 4; i++)
#pragma unroll
        for (int j = 0; j < 4; j++)
#pragma unroll
            for (int e = 0; e < 4; e++) d[i][j][e] = 0.f;

    for (int ch = 0; ch < nchunks; ch++) {
        const int kc = ch << 5;
        __syncthreads();
#pragma unroll
        for (int i = 0; i < 4; i++) {
            int idx = i * 256 + tid;
            int r = idx >> 3, c4 = (idx & 7) << 2;
            float4 va = *(const float4*)(A + (size_t)(row0 + r) * lda + kc + c4);
            float* pa = Ah + r * PLD + c4;
            float hx = to_tf32(va.x), hy = to_tf32(va.y),
                  hz = to_tf32(va.z), hw = to_tf32(va.w);
            pa[0] = hx; pa[1] = hy; pa[2] = hz; pa[3] = hw;
            if (NPASS == 3) {
                float* ql = Al + r * PLD + c4;
                ql[0] = to_tf32(va.x - hx); ql[1] = to_tf32(va.y - hy);
                ql[2] = to_tf32(va.z - hz); ql[3] = to_tf32(va.w - hw);
            }
            float4 vb = *(const float4*)(B + (size_t)(col0 + r) * ldb + kc + c4);
            float* pb = Bh + r * PLD + c4;
            hx = to_tf32(vb.x); hy = to_tf32(vb.y);
            hz = to_tf32(vb.z); hw = to_tf32(vb.w);
            pb[0] = hx; pb[1] = hy; pb[2] = hz; pb[3] = hw;
            if (NPASS == 3) {
                float* ql = Bl + r * PLD + c4;
                ql[0] = to_tf32(vb.x - hx); ql[1] = to_tf32(vb.y - hy);
                ql[2] = to_tf32(vb.z - hz); ql[3] = to_tf32(vb.w - hw);
            }
        }
        __syncthreads();

#pragma unroll
        for (int ks = 0; ks < 4; ks++) {
            const int k0 = ks << 3;
            uint32_t af[4][4], bf[4][2];
#pragma unroll
            for (int mt = 0; mt < 4; mt++) {
                const float* p = Ah + (m0 + (mt << 4) + g) * PLD + k0 + t;
                af[mt][0] = __float_as_uint(p[0]);
                af[mt][1] = __float_as_uint(p[8 * PLD]);
                af[mt][2] = __float_as_uint(p[4]);
                af[mt][3] = __float_as_uint(p[8 * PLD + 4]);
            }
#pragma unroll
            for (int nt = 0; nt < 4; nt++) {
                const float* p = Bh + (n0 + (nt << 3) + g) * PLD + k0 + t;
                bf[nt][0] = __float_as_uint(p[0]);
                bf[nt][1] = __float_as_uint(p[4]);
            }
#pragma unroll
            for (int mt = 0; mt < 4; mt++)
#pragma unroll
                for (int nt = 0; nt < 4; nt++)
                    MMA_TF32(d[mt][nt], af[mt], bf[nt]);

            if (NPASS == 3) {
                uint32_t lf[4][2];
#pragma unroll
                for (int nt = 0; nt < 4; nt++) {
                    const float* p = Bl + (n0 + (nt << 3) + g) * PLD + k0 + t;
                    lf[nt][0] = __float_as_uint(p[0]);
                    lf[nt][1] = __float_as_uint(p[4]);
                }
#pragma unroll
                for (int mt = 0; mt < 4; mt++)
#pragma unroll
                    for (int nt = 0; nt < 4; nt++)
                        MMA_TF32(d[mt][nt], af[mt], lf[nt]);
                uint32_t alf[4][4];
#pragma unroll
                for (int mt = 0; mt < 4; mt++) {
                    const float* p = Al + (m0 + (mt << 4) + g) * PLD + k0 + t;
                    alf[mt][0] = __float_as_uint(p[0]);
                    alf[mt][1] = __float_as_uint(p[8 * PLD]);
                    alf[mt][2] = __float_as_uint(p[4]);
                    alf[mt][3] = __float_as_uint(p[8 * PLD + 4]);
                }
#pragma unroll
                for (int mt = 0; mt < 4; mt++)
#pragma unroll
                    for (int nt = 0; nt < 4; nt++)
                        MMA_TF32(d[mt][nt], alf[mt], bf[nt]);
            }
        }
    }

    // epilogue: per (mt,nt): rows g,g+8; cols 2t,2t+1 (float2 stores)
#pragma unroll
    for (int mt = 0; mt < 4; mt++) {
#pragma unroll
        for (int nt = 0; nt < 4; nt++) {
            int c = col0 + n0 + (nt << 3) + (t << 1);
            float b0 = bias ? bias[c] : 0.f;
            float b1 = bias ? bias[c + 1] : 0.f;
#pragma unroll
            for (int half = 0; half < 2; half++) {
                int r = row0 + m0 + (mt << 4) + g + half * 8;
                float2 v;
                v.x = d[mt][nt][half * 2 + 0] * scale + b0;
                v.y = d[mt][nt][half * 2 + 1] * scale + b1;
                if (head_layout) {
                    int b_ = r >> 10, s_ = r & 1023;
                    int h_ = c >> 6, d_ = c & 63;
                    *(float2*)(C + (((size_t)(b_ * NH + h_) * SDIM + s_) << 6) + d_) = v;
                } else {
                    *(float2*)(C + (size_t)r * 1024 + c) = v;
                }
            }
        }
    }
}

// ---------------------------------------------------------------------------
// 1024x1024 transpose
// ---------------------------------------------------------------------------
__global__ __launch_bounds__(256)
void transpose_kernel(const float* __restrict__ in, float* __restrict__ out)
{
    __shared__ float tb[32][33];
    const int tx = threadIdx.x, ty = threadIdx.y;
    const int bx = blockIdx.x << 5, by = blockIdx.y << 5;
#pragma unroll
    for (int i = 0; i < 4; i++)
        tb[ty + i * 8][tx] = in[(size_t)(by + ty + i * 8) * 1024 + bx + tx];
    __syncthreads();
#pragma unroll
    for (int i = 0; i < 4; i++)
        out[(size_t)(bx + ty + i * 8) * 1024 + by + tx] = tb[tx][ty + i * 8];
}

// ---------------------------------------------------------------------------
// FFMA2 fp32 GEMM — Q/K projections (mask-critical exact precision)
// ---------------------------------------------------------------------------
#define PACK2(d, lo, hi) asm("mov.b64 %0, {%1, %2};" : "=l"(d) : "f"(lo), "f"(hi))
#define FMA2(acc, a, b)  asm("fma.rn.f32x2 %0, %1, %2, %0;" : "+l"(acc) : "l"(a), "l"(b))
#define UNPACK2(lo, hi, v) asm("mov.b64 {%0, %1}, %2;" : "=f"(lo), "=f"(hi) : "l"(v))

__global__ __launch_bounds__(256, 2)
void gemm_kernel(const float* __restrict__ A, const float* __restrict__ W,
                 const float* __restrict__ bias, float* __restrict__ out,
                 int head_layout)
{
    __shared__ __align__(16) float As[16][128];
    __shared__ __align__(16) float Ws[16][128];
    const int tid = threadIdx.x;
    const int tx = tid & 15;
    const int ty = tid >> 4;
    const int row0 = blockIdx.y << 7;
    const int col0 = blockIdx.x << 7;

    unsigned long long acc2[8][4];
#pragma unroll
    for (int i = 0; i < 8; i++)
#pragma unroll
        for (int j = 0; j < 4; j++) acc2[i][j] = 0ull;

    for (int kc = 0; kc < 1024; kc += 16) {
#pragma unroll
        for (int i = 0; i < 2; i++) {
            int l = i * 256 + tid;
            int ar = l >> 2, ac = (l & 3) << 2;
            float4 va = *(const float4*)(A + (size_t)(row0 + ar) * 1024 + kc + ac);
            As[ac + 0][ar] = va.x;
            As[ac + 1][ar] = va.y;
            As[ac + 2][ar] = va.z;
            As[ac + 3][ar] = va.w;
            int wr = l >> 5, wc = (l & 31) << 2;
            *(float4*)&Ws[wr][wc] = *(const float4*)(W + (size_t)(kc + wr) * 1024 + col0 + wc);
        }
        __syncthreads();
#pragma unroll
        for (int k = 0; k < 16; k++) {
            float a[8];
            *(float4*)&a[0] = *(const float4*)&As[k][ty << 2];
            *(float4*)&a[4] = *(const float4*)&As[k][64 + (ty << 2)];
            ulonglong2 t0 = *(const ulonglong2*)&Ws[k][tx << 2];
            ulonglong2 t1 = *(const ulonglong2*)&Ws[k][64 + (tx << 2)];
#pragma unroll
            for (int i = 0; i < 8; i++) {
                unsigned long long ad;
                PACK2(ad, a[i], a[i]);
                FMA2(acc2[i][0], ad, t0.x);
                FMA2(acc2[i][1], ad, t0.y);
                FMA2(acc2[i][2], ad, t1.x);
                FMA2(acc2[i][3], ad, t1.y);
            }
        }
        __syncthreads();
    }

#pragma unroll
    for (int i = 0; i < 8; i++) {
        int r = row0 + ((i < 4) ? ((ty << 2) + i) : (64 + (ty << 2) + (i - 4)));
#pragma unroll
        for (int jj = 0; jj < 2; jj++) {
            int c = col0 + jj * 64 + (tx << 2);
            float4 v;
            UNPACK2(v.x, v.y, acc2[i][jj * 2 + 0]);
            UNPACK2(v.z, v.w, acc2[i][jj * 2 + 1]);
            v.x += bias[c + 0];
            v.y += bias[c + 1];
            v.z += bias[c + 2];
            v.w += bias[c + 3];
            if (head_layout) {
                int b_ = r >> 10, s_ = r & 1023;
                int h_ = c >> 6, d_ = c & 63;
                *(float4*)(out + ((size_t)((b_ * NH + h_) * SDIM + s_)) * HD + d_) = v;
            } else {
                *(float4*)(out + (size_t)r * 1024 + c) = v;
            }
        }
    }
}

// ---------------------------------------------------------------------------
// Mask + softmax + sparse AV with exact fp32 fixup of candidate scores.
// Candidates = entries within 0.04 of (noisy) row max — covers the survivor
// band (0.004) + all Z-relevant terms (0.021) + >20 sigma of tf32 1-pass
// score noise. Candidate scores recomputed as exact fp32 dots from qh/kh
// (which are FFMA-exact), so every threshold decision is tensor-noise-free.
// ---------------------------------------------------------------------------
__global__ __launch_bounds__(256)
void mask_av_kernel(const float* __restrict__ sc,
                    const float* __restrict__ qh, const float* __restrict__ kh,
                    const float* __restrict__ vh, float* __restrict__ attn)
{
    __shared__ float rows[8][1024];
    __shared__ int   listK[8][64];
    __shared__ float listS[8][64];

    const int bh = blockIdx.y;
    const int q0 = blockIdx.x << 3;
    const int tid = threadIdx.x;

    const float* src = sc + ((size_t)bh * SDIM + q0) * SDIM;
    for (int i = tid; i < 8 * 1024 / 4; i += 256)
        *(float4*)&rows[0][i * 4] = *(const float4*)&src[(size_t)i * 4];
    __syncthreads();

    const int qi = tid >> 5;
    const int lane = tid & 31;
    float* row = rows[qi];
    const int q = q0 + qi;
    const float* qrow = qh + ((size_t)bh * SDIM + q) * HD;
    const float* khb = kh + (size_t)bh * SDIM * HD;
    const float* vb  = vh + (size_t)bh * SDIM * HD;

    // approx row max (tensor-noisy, band absorbs it)
    float m = -FLT_MAX;
    for (int k = lane; k < 1024; k += 32) m = fmaxf(m, row[k]);
#pragma unroll
    for (int o = 16; o > 0; o >>= 1) m = fmaxf(m, __shfl_xor_sync(0xffffffffu, m, o));

    const float band = m - 0.04f;
    int cnt = 0;
    for (int it = 0; it < 32; it++) {
        int k = it * 32 + lane;
        bool c = (row[k] >= band);
        unsigned bm = __ballot_sync(0xffffffffu, c);
        if (c) {
            int pos = cnt + __popc(bm & ((1u << lane) - 1u));
            if (pos < 64) listK[qi][pos] = k;
        }
        cnt += __popc(bm);
    }
    __syncwarp();

    float a0 = 0.f, a1 = 0.f;

    if (cnt <= 64) {
        // exact fp32 dot for every candidate (warp-cooperative)
        const float qa = qrow[lane], qb = qrow[lane + 32];
        for (int j = 0; j < cnt; j++) {
            const int k = listK[qi][j];
            const float* krow = khb + (size_t)k * HD;
            float p = qa * krow[lane] + qb * krow[lane + 32];
#pragma unroll
            for (int o = 16; o > 0; o >>= 1) p += __shfl_xor_sync(0xffffffffu, p, o);
            if (lane == 0) listS[qi][j] = p * 0.125f;
        }
        __syncwarp();

        float m_ex = -FLT_MAX;
        for (int j = 0; j < cnt; j++) m_ex = fmaxf(m_ex, listS[qi][j]);
        const float xm = m_ex / 0.001f;
        float Z = 0.f;
        for (int j = 0; j < cnt; j++) Z += expf(listS[qi][j] / 0.001f - xm);

        float m2 = -FLT_MAX;
        int nsurv = 0;
        for (int j = 0; j < cnt; j++) {
            float att = expf(listS[qi][j] / 0.001f - xm) / Z;
            if (att >= 0.019f) { m2 = fmaxf(m2, listS[qi][j]); nsurv++; }
        }
        if (nsurv > 0) {
            float wsum = 0.f;
            for (int j = 0; j < cnt; j++) {
                float att = expf(listS[qi][j] / 0.001f - xm) / Z;
                if (att >= 0.019f) wsum += expf(listS[qi][j] - m2);
            }
            for (int j = 0; j < cnt; j++) {
                float s = listS[qi][j];
                float att = expf(s / 0.001f - xm) / Z;
                if (att >= 0.019f) {
                    float wgt = expf(s - m2) / wsum;
                    const int k = listK[qi][j];
                    a0 += wgt * vb[(size_t)k * HD + lane];
                    a1 += wgt * vb[(size_t)k * HD + lane + 32];
                }
            }
        } else {
            for (int k = 0; k < 1024; k++) {
                a0 += vb[(size_t)k * HD + lane];
                a1 += vb[(size_t)k * HD + lane + 32];
            }
            a0 *= (1.f / 1024.f);
            a1 *= (1.f / 1024.f);
        }
    } else {
        // RARE: >64 near-ties — recompute whole row exactly
        for (int it = 0; it < 32; it++) {
            int k = it * 32 + lane;
            const float* krow = khb + (size_t)k * HD;
            float p = 0.f;
#pragma unroll
            for (int dd = 0; dd < 64; dd++) p += qrow[dd] * krow[dd];
            row[k] = p * 0.125f;
        }
        __syncwarp();
        float me = -FLT_MAX;
        for (int k = lane; k < 1024; k += 32) me = fmaxf(me, row[k]);
#pragma unroll
        for (int o = 16; o > 0; o >>= 1) me = fmaxf(me, __shfl_xor_sync(0xffffffffu, me, o));
        const float xm = me / 0.001f;
        float Z = 0.f;
        for (int k = lane; k < 1024; k += 32) Z += expf(row[k] / 0.001f - xm);
#pragma unroll
        for (int o = 16; o > 0; o >>= 1) Z += __shfl_xor_sync(0xffffffffu, Z, o);
        float m2 = -FLT_MAX;
        for (int k = lane; k < 1024; k += 32)
            if (expf(row[k] / 0.001f - xm) / Z >= 0.019f) m2 = fmaxf(m2, row[k]);
#pragma unroll
        for (int o = 16; o > 0; o >>= 1) m2 = fmaxf(m2, __shfl_xor_sync(0xffffffffu, m2, o));
        const bool any = (m2 > -1e37f);
        float wsum = 0.f;
        if (any) {
            for (int k = lane; k < 1024; k += 32) {
                float att = expf(row[k] / 0.001f - xm) / Z;
                if (att >= 0.019f) wsum += expf(row[k] - m2);
            }
#pragma unroll
            for (int o = 16; o > 0; o >>= 1) wsum += __shfl_xor_sync(0xffffffffu, wsum, o);
        }
        for (int k = 0; k < 1024; k++) {
            float wgt;
            if (!any) wgt = 1.f / 1024.f;
            else {
                float att = expf(row[k] / 0.001f - xm) / Z;
                wgt = (att >= 0.019f) ? expf(row[k] - m2) / wsum : 0.f;
            }
            a0 += wgt * vb[(size_t)k * HD + lane];
            a1 += wgt * vb[(size_t)k * HD + lane + 32];
        }
    }

    const int b_ = bh >> 4, h_ = bh & 15;
    float* dst = attn + ((size_t)(b_ * SDIM + q)) * DDIM + h_ * HD;
    dst[lane] = a0;
    dst[lane + 32] = a1;
}

// ---------------------------------------------------------------------------
extern "C" void kernel_launch(void* const* d_in, const int* in_sizes, int n_in,
                              void* d_out, int out_size)
{
    const float* Q  = (const float*)d_in[0];
    const float* K  = (const float*)d_in[1];
    const float* V  = (const float*)d_in[2];
    const float* Wq = (const float*)d_in[3];
    const float* bq = (const float*)d_in[4];
    const float* Wk = (const float*)d_in[5];
    const float* bk = (const float*)d_in[6];
    const float* Wv = (const float*)d_in[7];
    const float* bv = (const float*)d_in[8];
    const float* Wo = (const float*)d_in[9];
    const float* bo = (const float*)d_in[10];

    float *qh, *kh, *vh, *scr, *attn, *wvT, *woT;
    cudaGetSymbolAddress((void**)&qh,   g_qh);
    cudaGetSymbolAddress((void**)&kh,   g_kh);
    cudaGetSymbolAddress((void**)&vh,   g_vh);
    cudaGetSymbolAddress((void**)&scr,  g_sc);
    cudaGetSymbolAddress((void**)&attn, g_attn);
    cudaGetSymbolAddress((void**)&wvT,  g_wvT);
    cudaGetSymbolAddress((void**)&woT,  g_woT);

    const int SM3 = 4 * PLANE * 4;   // 73728 B
    const int SM1 = 2 * PLANE * 4;   // 36864 B
    cudaFuncSetAttribute(mma_gemm<3>, cudaFuncAttributeMaxDynamicSharedMemorySize, SM3);
    cudaFuncSetAttribute(mma_gemm<1>, cudaFuncAttributeMaxDynamicSharedMemorySize, SM1);

    // weight transposes for tensor GEMMs
    dim3 tb(32, 8), tg(32, 32);
    transpose_kernel<<<tg, tb>>>(Wv, wvT);
    transpose_kernel<<<tg, tb>>>(Wo, woT);

    // Q,K projections: exact fp32 FFMA2 (mask-critical)
    dim3 gproj(DDIM / 128, MTOT / 128);
    gemm_kernel<<<gproj, 256>>>(Q, Wq, bq, qh, 1);
    gemm_kernel<<<gproj, 256>>>(K, Wk, bk, kh, 1);

    // V projection: tensor 3xTF32
    mma_gemm<3><<<dim3(8, 32, 1), 256, SM3>>>(V, 0, 1024, wvT, 0, 1024,
                                              bv, vh, 0, 32, 1.0f, 1);
    // scores: tensor 1xTF32 (mask fixup absorbs noise), batched over bh
    mma_gemm<1><<<dim3(8, 8, 64), 256, SM1>>>(qh, (size_t)SDIM * HD, 64,
                                              kh, (size_t)SDIM * HD, 64,
                                              nullptr, scr, (size_t)SDIM * SDIM,
                                              2, 0.125f, 0);
    // mask + sparse AV with exact fixup
    mask_av_kernel<<<dim3(SDIM / 8, NBH), 256>>>(scr, qh, kh, vh, attn);

    // output projection: tensor 3xTF32
    mma_gemm<3><<<dim3(8, 32, 1), 256, SM3>>>(attn, 0, 1024, woT, 0, 1024,
                                              bo, (float*)d_out, 0, 32, 1.0f, 0);
}

// round 5
// speedup vs baseline: 1.1726x; 1.0924x over previous
#include <cuda_runtime.h>
#include <cuda_bf16.h>
#include <math.h>
#include <stdint.h>
#include <float.h>

#define SDIM 1024
#define DDIM 1024
#define NH 16
#define HD 64
#define NBH 64
#define MTOT 4096

// ---------------- scratch (__device__ globals; no runtime alloc) ------------
__device__ float g_qh[NBH * SDIM * HD];
__device__ float g_kh[NBH * SDIM * HD];
__device__ float g_vh[NBH * SDIM * HD];
__device__ float g_sc[(size_t)NBH * SDIM * SDIM];   // 256 MB
__device__ float g_attn[(size_t)MTOT * DDIM];
__device__ float g_wqT[DDIM * DDIM];
__device__ float g_wkT[DDIM * DDIM];
__device__ float g_wvT[DDIM * DDIM];
__device__ float g_woT[DDIM * DDIM];

// ---------------- helpers ----------------------------------------------------
__device__ __forceinline__ float to_tf32(float x) {
    uint32_t u;
    asm("cvt.rna.tf32.f32 %0, %1;" : "=r"(u) : "f"(x));
    return __uint_as_float(u);
}

#define MMA_TF32(d, a, b) \
    asm volatile("mma.sync.aligned.m16n8k8.row.col.f32.tf32.tf32.f32 " \
                 "{%0,%1,%2,%3}, {%4,%5,%6,%7}, {%8,%9}, {%0,%1,%2,%3};" \
                 : "+f"((d)[0]), "+f"((d)[1]), "+f"((d)[2]), "+f"((d)[3]) \
                 : "r"((a)[0]), "r"((a)[1]), "r"((a)[2]), "r"((a)[3]), \
                   "r"((b)[0]), "r"((b)[1]))

#define MMA_BF16(d, a0, a1, a2, a3, b0, b1) \
    asm volatile("mma.sync.aligned.m16n8k16.row.col.f32.bf16.bf16.f32 " \
                 "{%0,%1,%2,%3}, {%4,%5,%6,%7}, {%8,%9}, {%0,%1,%2,%3};" \
                 : "+f"((d)[0]), "+f"((d)[1]), "+f"((d)[2]), "+f"((d)[3]) \
                 : "r"(a0), "r"(a1), "r"(a2), "r"(a3), "r"(b0), "r"(b1))

// plane stride: 36 floats/row -> frag-load banks (4g+t) conflict-free
#define PLD 36
#define PLANE (128 * PLD)

// ---------------------------------------------------------------------------
// Tensor-pipe GEMM via mma.sync tf32 (proven in R4).
// NPASS=3: tf32 split (hh+hl+lh). NPASS=1: plain tf32 (scores path).
// ---------------------------------------------------------------------------
template <int NPASS>
__global__ __launch_bounds__(256, 1)
void mma_gemm(const float* __restrict__ Abase, size_t sA, int lda,
              const float* __restrict__ Bbase, size_t sB, int ldb,
              const float* __restrict__ bias,
              float* __restrict__ Cbase, size_t sC,
              int nchunks, float scale, int head_layout)
{
    extern __shared__ __align__(16) float smf[];
    float* Ah = smf;
    float* Bh = smf + PLANE;
    float* Al = smf + 2 * PLANE;
    float* Bl = smf + 3 * PLANE;

    const int tid = threadIdx.x;
    const int w = tid >> 5;
    const int lane = tid & 31;
    const int g = lane >> 2;
    const int t = lane & 3;
    const int m0 = (w & 1) << 6;
    const int n0 = (w >> 1) << 5;

    const float* A = Abase + (size_t)blockIdx.z * sA;
    const float* B = Bbase + (size_t)blockIdx.z * sB;
    float* C = Cbase + (size_t)blockIdx.z * sC;
    const int row0 = blockIdx.y << 7;
    const int col0 = blockIdx.x << 7;

    float d[4][4][4];
#pragma unroll
    for (int i = 0; i < 4; i++)
#pragma unroll
        for (int j = 0; j < 4; j++)
#pragma unroll
            for (int e = 0; e < 4; e++) d[i][j][e] = 0.f;

    for (int ch = 0; ch < nchunks; ch++) {
        const int kc = ch << 5;
        __syncthreads();
#pragma unroll
        for (int i = 0; i < 4; i++) {
            int idx = i * 256 + tid;
            int r = idx >> 3, c4 = (idx & 7) << 2;
            float4 va = *(const float4*)(A + (size_t)(row0 + r) * lda + kc + c4);
            float* pa = Ah + r * PLD + c4;
            float hx = to_tf32(va.x), hy = to_tf32(va.y),
                  hz = to_tf32(va.z), hw = to_tf32(va.w);
            pa[0] = hx; pa[1] = hy; pa[2] = hz; pa[3] = hw;
            if (NPASS == 3) {
                float* ql = Al + r * PLD + c4;
                ql[0] = to_tf32(va.x - hx); ql[1] = to_tf32(va.y - hy);
                ql[2] = to_tf32(va.z - hz); ql[3] = to_tf32(va.w - hw);
            }
            float4 vb = *(const float4*)(B + (size_t)(col0 + r) * ldb + kc + c4);
            float* pb = Bh + r * PLD + c4;
            hx = to_tf32(vb.x); hy = to_tf32(vb.y);
            hz = to_tf32(vb.z); hw = to_tf32(vb.w);
            pb[0] = hx; pb[1] = hy; pb[2] = hz; pb[3] = hw;
            if (NPASS == 3) {
                float* ql = Bl + r * PLD + c4;
                ql[0] = to_tf32(vb.x - hx); ql[1] = to_tf32(vb.y - hy);
                ql[2] = to_tf32(vb.z - hz); ql[3] = to_tf32(vb.w - hw);
            }
        }
        __syncthreads();

#pragma unroll
        for (int ks = 0; ks < 4; ks++) {
            const int k0 = ks << 3;
            uint32_t af[4][4], bf[4][2];
#pragma unroll
            for (int mt = 0; mt < 4; mt++) {
                const float* p = Ah + (m0 + (mt << 4) + g) * PLD + k0 + t;
                af[mt][0] = __float_as_uint(p[0]);
                af[mt][1] = __float_as_uint(p[8 * PLD]);
                af[mt][2] = __float_as_uint(p[4]);
                af[mt][3] = __float_as_uint(p[8 * PLD + 4]);
            }
#pragma unroll
            for (int nt = 0; nt < 4; nt++) {
                const float* p = Bh + (n0 + (nt << 3) + g) * PLD + k0 + t;
                bf[nt][0] = __float_as_uint(p[0]);
                bf[nt][1] = __float_as_uint(p[4]);
            }
#pragma unroll
            for (int mt = 0; mt < 4; mt++)
#pragma unroll
                for (int nt = 0; nt < 4; nt++)
                    MMA_TF32(d[mt][nt], af[mt], bf[nt]);

            if (NPASS == 3) {
                uint32_t lf[4][2];
#pragma unroll
                for (int nt = 0; nt < 4; nt++) {
                    const float* p = Bl + (n0 + (nt << 3) + g) * PLD + k0 + t;
                    lf[nt][0] = __float_as_uint(p[0]);
                    lf[nt][1] = __float_as_uint(p[4]);
                }
#pragma unroll
                for (int mt = 0; mt < 4; mt++)
#pragma unroll
                    for (int nt = 0; nt < 4; nt++)
                        MMA_TF32(d[mt][nt], af[mt], lf[nt]);
                uint32_t alf[4][4];
#pragma unroll
                for (int mt = 0; mt < 4; mt++) {
                    const float* p = Al + (m0 + (mt << 4) + g) * PLD + k0 + t;
                    alf[mt][0] = __float_as_uint(p[0]);
                    alf[mt][1] = __float_as_uint(p[8 * PLD]);
                    alf[mt][2] = __float_as_uint(p[4]);
                    alf[mt][3] = __float_as_uint(p[8 * PLD + 4]);
                }
#pragma unroll
                for (int mt = 0; mt < 4; mt++)
#pragma unroll
                    for (int nt = 0; nt < 4; nt++)
                        MMA_TF32(d[mt][nt], alf[mt], bf[nt]);
            }
        }
    }

#pragma unroll
    for (int mt = 0; mt < 4; mt++) {
#pragma unroll
        for (int nt = 0; nt < 4; nt++) {
            int c = col0 + n0 + (nt << 3) + (t << 1);
            float b0 = bias ? bias[c] : 0.f;
            float b1 = bias ? bias[c + 1] : 0.f;
#pragma unroll
            for (int half = 0; half < 2; half++) {
                int r = row0 + m0 + (mt << 4) + g + half * 8;
                float2 v;
                v.x = d[mt][nt][half * 2 + 0] * scale + b0;
                v.y = d[mt][nt][half * 2 + 1] * scale + b1;
                if (head_layout) {
                    int b_ = r >> 10, s_ = r & 1023;
                    int h_ = c >> 6, d_ = c & 63;
                    *(float2*)(C + (((size_t)(b_ * NH + h_) * SDIM + s_) << 6) + d_) = v;
                } else {
                    *(float2*)(C + (size_t)r * 1024 + c) = v;
                }
            }
        }
    }
}

// ---------------------------------------------------------------------------
// bf16 3-product GEMM (hh + hl + lh), m16n8k16. Error ~1.5e-5 rel — used for
// V and O projections only (linear error propagation).
// SMEM layout: per row 16 logical b32 words (32 bf16), stored with in-group
// permutation phys = (j&3)*2 + (j>>2) per 8-word k16 group so that the frag
// pairs (a0,a2)/(a1,a3)/(b0,b1) are adjacent -> LDS.64. Row stride 20 words
// -> conflict-free (g*20 mod 32 all-distinct bank groups).
// ---------------------------------------------------------------------------
#define BPLD 20
#define BPLANE (128 * BPLD)

__device__ __forceinline__ uint32_t pack_bf16(float a, float b) {
    __nv_bfloat162 v = __floats2bfloat162_rn(a, b);
    return *reinterpret_cast<uint32_t*>(&v);
}

__global__ __launch_bounds__(256, 1)
void mma_gemm_bf16(const float* __restrict__ A, int lda,
                   const float* __restrict__ B, int ldb,
                   const float* __restrict__ bias,
                   float* __restrict__ C, float scale, int head_layout)
{
    __shared__ __align__(16) uint32_t Ah[BPLANE];
    __shared__ __align__(16) uint32_t Al[BPLANE];
    __shared__ __align__(16) uint32_t Bh_[BPLANE];
    __shared__ __align__(16) uint32_t Bl[BPLANE];

    const int tid = threadIdx.x;
    const int w = tid >> 5;
    const int lane = tid & 31;
    const int g = lane >> 2;
    const int t = lane & 3;
    const int m0 = (w & 1) << 6;
    const int n0 = (w >> 1) << 5;
    const int row0 = blockIdx.y << 7;
    const int col0 = blockIdx.x << 7;

    float d[4][4][4];
#pragma unroll
    for (int i = 0; i < 4; i++)
#pragma unroll
        for (int j = 0; j < 4; j++)
#pragma unroll
            for (int e = 0; e < 4; e++) d[i][j][e] = 0.f;

    // staging slot: r = idx>>3 (row), s = idx&7 -> k cols s*4..s*4+3
    // logical words 2s, 2s+1 -> phys group (s>>2)*8 + p0, p0+2
    const int s_ = tid & 7;
    const int j0 = (2 * s_) & 7;
    const int phys0 = ((s_ >> 2) << 3) + ((j0 & 3) << 1) + (j0 >> 2);

    for (int ch = 0; ch < 32; ch++) {
        const int kc = ch << 5;
        __syncthreads();
#pragma unroll
        for (int i = 0; i < 4; i++) {
            int idx = i * 256 + tid;
            int r = idx >> 3;
            int wo = r * BPLD + phys0;
            float4 va = *(const float4*)(A + (size_t)(row0 + r) * lda + kc + s_ * 4);
            float hx = __bfloat162float(__float2bfloat16_rn(va.x));
            float hy = __bfloat162float(__float2bfloat16_rn(va.y));
            float hz = __bfloat162float(__float2bfloat16_rn(va.z));
            float hw = __bfloat162float(__float2bfloat16_rn(va.w));
            Ah[wo]     = pack_bf16(hx, hy);
            Ah[wo + 2] = pack_bf16(hz, hw);
            Al[wo]     = pack_bf16(va.x - hx, va.y - hy);
            Al[wo + 2] = pack_bf16(va.z - hz, va.w - hw);
            float4 vb = *(const float4*)(B + (size_t)(col0 + r) * ldb + kc + s_ * 4);
            hx = __bfloat162float(__float2bfloat16_rn(vb.x));
            hy = __bfloat162float(__float2bfloat16_rn(vb.y));
            hz = __bfloat162float(__float2bfloat16_rn(vb.z));
            hw = __bfloat162float(__float2bfloat16_rn(vb.w));
            Bh_[wo]     = pack_bf16(hx, hy);
            Bh_[wo + 2] = pack_bf16(hz, hw);
            Bl[wo]     = pack_bf16(vb.x - hx, vb.y - hy);
            Bl[wo + 2] = pack_bf16(vb.z - hz, vb.w - hw);
        }
        __syncthreads();

#pragma unroll
        for (int ks = 0; ks < 2; ks++) {
            const int kw = (ks << 3) + (t << 1);
            uint2 aH[4][2], aL[4][2], bH[4], bL[4];
#pragma unroll
            for (int mt = 0; mt < 4; mt++) {
                int rw = (m0 + (mt << 4) + g) * BPLD + kw;
                aH[mt][0] = *(const uint2*)&Ah[rw];
                aH[mt][1] = *(const uint2*)&Ah[rw + 8 * BPLD];
                aL[mt][0] = *(const uint2*)&Al[rw];
                aL[mt][1] = *(const uint2*)&Al[rw + 8 * BPLD];
            }
#pragma unroll
            for (int nt = 0; nt < 4; nt++) {
                int rw = (n0 + (nt << 3) + g) * BPLD + kw;
                bH[nt] = *(const uint2*)&Bh_[rw];
                bL[nt] = *(const uint2*)&Bl[rw];
            }
#pragma unroll
            for (int mt = 0; mt < 4; mt++)
#pragma unroll
                for (int nt = 0; nt < 4; nt++) {
                    MMA_BF16(d[mt][nt], aH[mt][0].x, aH[mt][1].x, aH[mt][0].y, aH[mt][1].y,
                             bH[nt].x, bH[nt].y);
                    MMA_BF16(d[mt][nt], aH[mt][0].x, aH[mt][1].x, aH[mt][0].y, aH[mt][1].y,
                             bL[nt].x, bL[nt].y);
                    MMA_BF16(d[mt][nt], aL[mt][0].x, aL[mt][1].x, aL[mt][0].y, aL[mt][1].y,
                             bH[nt].x, bH[nt].y);
                }
        }
    }

#pragma unroll
    for (int mt = 0; mt < 4; mt++) {
#pragma unroll
        for (int nt = 0; nt < 4; nt++) {
            int c = col0 + n0 + (nt << 3) + (t << 1);
            float b0 = bias ? bias[c] : 0.f;
            float b1 = bias ? bias[c + 1] : 0.f;
#pragma unroll
            for (int half = 0; half < 2; half++) {
                int r = row0 + m0 + (mt << 4) + g + half * 8;
                float2 v;
                v.x = d[mt][nt][half * 2 + 0] * scale + b0;
                v.y = d[mt][nt][half * 2 + 1] * scale + b1;
                if (head_layout) {
                    int b_ = r >> 10, s2 = r & 1023;
                    int h_ = c >> 6, d_ = c & 63;
                    *(float2*)(C + (((size_t)(b_ * NH + h_) * SDIM + s2) << 6) + d_) = v;
                } else {
                    *(float2*)(C + (size_t)r * 1024 + c) = v;
                }
            }
        }
    }
}

// ---------------------------------------------------------------------------
// 1024x1024 transpose
// ---------------------------------------------------------------------------
__global__ __launch_bounds__(256)
void transpose_kernel(const float* __restrict__ in, float* __restrict__ out)
{
    __shared__ float tb[32][33];
    const int tx = threadIdx.x, ty = threadIdx.y;
    const int bx = blockIdx.x << 5, by = blockIdx.y << 5;
#pragma unroll
    for (int i = 0; i < 4; i++)
        tb[ty + i * 8][tx] = in[(size_t)(by + ty + i * 8) * 1024 + bx + tx];
    __syncthreads();
#pragma unroll
    for (int i = 0; i < 4; i++)
        out[(size_t)(bx + ty + i * 8) * 1024 + by + tx] = tb[tx][ty + i * 8];
}

// ---------------------------------------------------------------------------
// Mask + softmax + sparse AV with exact fp32 fixup (unchanged from R4).
// ---------------------------------------------------------------------------
__global__ __launch_bounds__(256)
void mask_av_kernel(const float* __restrict__ sc,
                    const float* __restrict__ qh, const float* __restrict__ kh,
                    const float* __restrict__ vh, float* __restrict__ attn)
{
    __shared__ float rows[8][1024];
    __shared__ int   listK[8][64];
    __shared__ float listS[8][64];

    const int bh = blockIdx.y;
    const int q0 = blockIdx.x << 3;
    const int tid = threadIdx.x;

    const float* src = sc + ((size_t)bh * SDIM + q0) * SDIM;
    for (int i = tid; i < 8 * 1024 / 4; i += 256)
        *(float4*)&rows[0][i * 4] = *(const float4*)&src[(size_t)i * 4];
    __syncthreads();

    const int qi = tid >> 5;
    const int lane = tid & 31;
    float* row = rows[qi];
    const int q = q0 + qi;
    const float* qrow = qh + ((size_t)bh * SDIM + q) * HD;
    const float* khb = kh + (size_t)bh * SDIM * HD;
    const float* vb  = vh + (size_t)bh * SDIM * HD;

    float m = -FLT_MAX;
    for (int k = lane; k < 1024; k += 32) m = fmaxf(m, row[k]);
#pragma unroll
    for (int o = 16; o > 0; o >>= 1) m = fmaxf(m, __shfl_xor_sync(0xffffffffu, m, o));

    const float band = m - 0.04f;
    int cnt = 0;
    for (int it = 0; it < 32; it++) {
        int k = it * 32 + lane;
        bool c = (row[k] >= band);
        unsigned bm = __ballot_sync(0xffffffffu, c);
        if (c) {
            int pos = cnt + __popc(bm & ((1u << lane) - 1u));
            if (pos < 64) listK[qi][pos] = k;
        }
        cnt += __popc(bm);
    }
    __syncwarp();

    float a0 = 0.f, a1 = 0.f;

    if (cnt <= 64) {
        const float qa = qrow[lane], qb = qrow[lane + 32];
        for (int j = 0; j < cnt; j++) {
            const int k = listK[qi][j];
            const float* krow = khb + (size_t)k * HD;
            float p = qa * krow[lane] + qb * krow[lane + 32];
#pragma unroll
            for (int o = 16; o > 0; o >>= 1) p += __shfl_xor_sync(0xffffffffu, p, o);
            if (lane == 0) listS[qi][j] = p * 0.125f;
        }
        __syncwarp();

        float m_ex = -FLT_MAX;
        for (int j = 0; j < cnt; j++) m_ex = fmaxf(m_ex, listS[qi][j]);
        const float xm = m_ex / 0.001f;
        float Z = 0.f;
        for (int j = 0; j < cnt; j++) Z += expf(listS[qi][j] / 0.001f - xm);

        float m2 = -FLT_MAX;
        int nsurv = 0;
        for (int j = 0; j < cnt; j++) {
            float att = expf(listS[qi][j] / 0.001f - xm) / Z;
            if (att >= 0.019f) { m2 = fmaxf(m2, listS[qi][j]); nsurv++; }
        }
        if (nsurv > 0) {
            float wsum = 0.f;
            for (int j = 0; j < cnt; j++) {
                float att = expf(listS[qi][j] / 0.001f - xm) / Z;
                if (att >= 0.019f) wsum += expf(listS[qi][j] - m2);
            }
            for (int j = 0; j < cnt; j++) {
                float s = listS[qi][j];
                float att = expf(s / 0.001f - xm) / Z;
                if (att >= 0.019f) {
                    float wgt = expf(s - m2) / wsum;
                    const int k = listK[qi][j];
                    a0 += wgt * vb[(size_t)k * HD + lane];
                    a1 += wgt * vb[(size_t)k * HD + lane + 32];
                }
            }
        } else {
            for (int k = 0; k < 1024; k++) {
                a0 += vb[(size_t)k * HD + lane];
                a1 += vb[(size_t)k * HD + lane + 32];
            }
            a0 *= (1.f / 1024.f);
            a1 *= (1.f / 1024.f);
        }
    } else {
        for (int it = 0; it < 32; it++) {
            int k = it * 32 + lane;
            const float* krow = khb + (size_t)k * HD;
            float p = 0.f;
#pragma unroll
            for (int dd = 0; dd < 64; dd++) p += qrow[dd] * krow[dd];
            row[k] = p * 0.125f;
        }
        __syncwarp();
        float me = -FLT_MAX;
        for (int k = lane; k < 1024; k += 32) me = fmaxf(me, row[k]);
#pragma unroll
        for (int o = 16; o > 0; o >>= 1) me = fmaxf(me, __shfl_xor_sync(0xffffffffu, me, o));
        const float xm = me / 0.001f;
        float Z = 0.f;
        for (int k = lane; k < 1024; k += 32) Z += expf(row[k] / 0.001f - xm);
#pragma unroll
        for (int o = 16; o > 0; o >>= 1) Z += __shfl_xor_sync(0xffffffffu, Z, o);
        float m2 = -FLT_MAX;
        for (int k = lane; k < 1024; k += 32)
            if (expf(row[k] / 0.001f - xm) / Z >= 0.019f) m2 = fmaxf(m2, row[k]);
#pragma unroll
        for (int o = 16; o > 0; o >>= 1) m2 = fmaxf(m2, __shfl_xor_sync(0xffffffffu, m2, o));
        const bool any = (m2 > -1e37f);
        float wsum = 0.f;
        if (any) {
            for (int k = lane; k < 1024; k += 32) {
                float att = expf(row[k] / 0.001f - xm) / Z;
                if (att >= 0.019f) wsum += expf(row[k] - m2);
            }
#pragma unroll
            for (int o = 16; o > 0; o >>= 1) wsum += __shfl_xor_sync(0xffffffffu, wsum, o);
        }
        for (int k = 0; k < 1024; k++) {
            float wgt;
            if (!any) wgt = 1.f / 1024.f;
            else {
                float att = expf(row[k] / 0.001f - xm) / Z;
                wgt = (att >= 0.019f) ? expf(row[k] - m2) / wsum : 0.f;
            }
            a0 += wgt * vb[(size_t)k * HD + lane];
            a1 += wgt * vb[(size_t)k * HD + lane + 32];
        }
    }

    const int b_ = bh >> 4, h_ = bh & 15;
    float* dst = attn + ((size_t)(b_ * SDIM + q)) * DDIM + h_ * HD;
    dst[lane] = a0;
    dst[lane + 32] = a1;
}

// ---------------------------------------------------------------------------
extern "C" void kernel_launch(void* const* d_in, const int* in_sizes, int n_in,
                              void* d_out, int out_size)
{
    const float* Q  = (const float*)d_in[0];
    const float* K  = (const float*)d_in[1];
    const float* V  = (const float*)d_in[2];
    const float* Wq = (const float*)d_in[3];
    const float* bq = (const float*)d_in[4];
    const float* Wk = (const float*)d_in[5];
    const float* bk = (const float*)d_in[6];
    const float* Wv = (const float*)d_in[7];
    const float* bv = (const float*)d_in[8];
    const float* Wo = (const float*)d_in[9];
    const float* bo = (const float*)d_in[10];

    float *qh, *kh, *vh, *scr, *attn, *wqT, *wkT, *wvT, *woT;
    cudaGetSymbolAddress((void**)&qh,   g_qh);
    cudaGetSymbolAddress((void**)&kh,   g_kh);
    cudaGetSymbolAddress((void**)&vh,   g_vh);
    cudaGetSymbolAddress((void**)&scr,  g_sc);
    cudaGetSymbolAddress((void**)&attn, g_attn);
    cudaGetSymbolAddress((void**)&wqT,  g_wqT);
    cudaGetSymbolAddress((void**)&wkT,  g_wkT);
    cudaGetSymbolAddress((void**)&wvT,  g_wvT);
    cudaGetSymbolAddress((void**)&woT,  g_woT);

    const int SM3 = 4 * PLANE * 4;   // 73728 B
    const int SM1 = 2 * PLANE * 4;   // 36864 B
    cudaFuncSetAttribute(mma_gemm<3>, cudaFuncAttributeMaxDynamicSharedMemorySize, SM3);
    cudaFuncSetAttribute(mma_gemm<1>, cudaFuncAttributeMaxDynamicSharedMemorySize, SM1);

    // weight transposes
    dim3 tb(32, 8), tg(32, 32);
    transpose_kernel<<<tg, tb>>>(Wq, wqT);
    transpose_kernel<<<tg, tb>>>(Wk, wkT);
    transpose_kernel<<<tg, tb>>>(Wv, wvT);
    transpose_kernel<<<tg, tb>>>(Wo, woT);

    // Q,K projections: tensor 3xTF32 (fp32-accumulation-class error)
    mma_gemm<3><<<dim3(8, 32, 1), 256, SM3>>>(Q, 0, 1024, wqT, 0, 1024,
                                              bq, qh, 0, 32, 1.0f, 1);
    mma_gemm<3><<<dim3(8, 32, 1), 256, SM3>>>(K, 0, 1024, wkT, 0, 1024,
                                              bk, kh, 0, 32, 1.0f, 1);
    // V projection: bf16 3-product (linear error, ~1.5e-5)
    mma_gemm_bf16<<<dim3(8, 32, 1), 256>>>(V, 1024, wvT, 1024, bv, vh, 1.0f, 1);

    // scores: tensor 1xTF32 (band + exact fixup absorbs noise)
    mma_gemm<1><<<dim3(8, 8, 64), 256, SM1>>>(qh, (size_t)SDIM * HD, 64,
                                              kh, (size_t)SDIM * HD, 64,
                                              nullptr, scr, (size_t)SDIM * SDIM,
                                              2, 0.125f, 0);
    // mask + sparse AV with exact fixup
    mask_av_kernel<<<dim3(SDIM / 8, NBH), 256>>>(scr, qh, kh, vh, attn);

    // output projection: bf16 3-product
    mma_gemm_bf16<<<dim3(8, 32, 1), 256>>>(attn, 1024, woT, 1024, bo,
                                           (float*)d_out, 1.0f, 0);
}

// round 6
// speedup vs baseline: 1.4115x; 1.2037x over previous
#include <cuda_runtime.h>
#include <cuda_bf16.h>
#include <math.h>
#include <stdint.h>
#include <float.h>

#define SDIM 1024
#define DDIM 1024
#define NH 16
#define HD 64
#define NBH 64
#define MTOT 4096

// ---------------- scratch (__device__ globals; no runtime alloc) ------------
__device__ float g_qh[NBH * SDIM * HD];
__device__ float g_kh[NBH * SDIM * HD];
__device__ float g_vh[NBH * SDIM * HD];
__device__ float g_attn[(size_t)MTOT * DDIM];
__device__ float g_wqT[DDIM * DDIM];
__device__ float g_wkT[DDIM * DDIM];
__device__ float g_wvT[DDIM * DDIM];
__device__ float g_woT[DDIM * DDIM];

// ---------------- helpers ----------------------------------------------------
__device__ __forceinline__ float to_tf32(float x) {
    uint32_t u;
    asm("cvt.rna.tf32.f32 %0, %1;" : "=r"(u) : "f"(x));
    return __uint_as_float(u);
}

#define MMA_TF32(d, a, b) \
    asm volatile("mma.sync.aligned.m16n8k8.row.col.f32.tf32.tf32.f32 " \
                 "{%0,%1,%2,%3}, {%4,%5,%6,%7}, {%8,%9}, {%0,%1,%2,%3};" \
                 : "+f"((d)[0]), "+f"((d)[1]), "+f"((d)[2]), "+f"((d)[3]) \
                 : "r"((a)[0]), "r"((a)[1]), "r"((a)[2]), "r"((a)[3]), \
                   "r"((b)[0]), "r"((b)[1]))

#define MMA_BF16(d, a0, a1, a2, a3, b0, b1) \
    asm volatile("mma.sync.aligned.m16n8k16.row.col.f32.bf16.bf16.f32 " \
                 "{%0,%1,%2,%3}, {%4,%5,%6,%7}, {%8,%9}, {%0,%1,%2,%3};" \
                 : "+f"((d)[0]), "+f"((d)[1]), "+f"((d)[2]), "+f"((d)[3]) \
                 : "r"(a0), "r"(a1), "r"(a2), "r"(a3), "r"(b0), "r"(b1))

// monotone float<->uint encoding for atomicMax on floats
__device__ __forceinline__ unsigned fenc(float f) {
    unsigned u = __float_as_uint(f);
    return (u & 0x80000000u) ? ~u : (u | 0x80000000u);
}
__device__ __forceinline__ float fdec(unsigned u) {
    unsigned v = (u & 0x80000000u) ? (u & 0x7FFFFFFFu) : ~u;
    return __uint_as_float(v);
}

// ---------------------------------------------------------------------------
// FUSED scores + mask + sparse AV. g_sc eliminated.
// Block = (q-tile of 128, bh). Two passes of 1-pass-tf32 mma over 8 key
// chunks: pass0 -> per-row max; pass1 -> in-band candidate lists (sorted for
// determinism). Phase 3 = exact fp32 fixup + softmax decisions + sparse AV
// (identical math to R5's proven mask_av_kernel).
// ---------------------------------------------------------------------------
#define ALD 68
#define F_SMEM (34816 + 34816 + 512 + 512 + 8192 + 8192)   // 87040 B

__global__ __launch_bounds__(256, 2)
void fused_scores_mask(const float* __restrict__ qh, const float* __restrict__ kh,
                       const float* __restrict__ vh, float* __restrict__ attn)
{
    extern __shared__ __align__(16) char fsm[];
    float*    Ap      = (float*)fsm;                  // 128 x 68 tf32 q
    float*    Bp      = (float*)(fsm + 34816);        // 128 x 68 tf32 k chunk
    unsigned* rowmaxU = (unsigned*)(fsm + 69632);     // 128
    int*      cntI    = (int*)(fsm + 70144);          // 128
    int*      listKs  = (int*)(fsm + 70656);          // 128 x 16
    float*    listSs  = (float*)(fsm + 78848);        // 128 x 16

    const int tid = threadIdx.x;
    const int w = tid >> 5;
    const int lane = tid & 31;
    const int g = lane >> 2;
    const int t = lane & 3;
    const int m0 = (w & 1) << 6;
    const int n0 = (w >> 1) << 5;
    const int bh = blockIdx.y;
    const int q0 = blockIdx.x << 7;

    const float* qbase = qh + ((size_t)bh * SDIM + q0) * HD;
    const float* kbh   = kh + (size_t)bh * SDIM * HD;
    const float* vb    = vh + (size_t)bh * SDIM * HD;

    if (tid < 128) { rowmaxU[tid] = 0u; cntI[tid] = 0; }

    // load q tile as tf32 (1-pass precision — fixup absorbs noise)
#pragma unroll
    for (int i = 0; i < 8; i++) {
        int idx = i * 256 + tid;              // 2048 float4s
        int r = idx >> 4, c4 = (idx & 15) << 2;
        float4 v = *(const float4*)(qbase + (size_t)r * HD + c4);
        float* p = Ap + r * ALD + c4;
        p[0] = to_tf32(v.x); p[1] = to_tf32(v.y);
        p[2] = to_tf32(v.z); p[3] = to_tf32(v.w);
    }
    __syncthreads();

    for (int pass = 0; pass < 2; pass++) {
        for (int ch = 0; ch < 8; ch++) {
            __syncthreads();   // protect Bp reuse + (pass1) rowmax visibility
#pragma unroll
            for (int i = 0; i < 8; i++) {
                int idx = i * 256 + tid;
                int r = idx >> 4, c4 = (idx & 15) << 2;
                float4 v = *(const float4*)(kbh + (size_t)(ch * 128 + r) * HD + c4);
                float* p = Bp + r * ALD + c4;
                p[0] = to_tf32(v.x); p[1] = to_tf32(v.y);
                p[2] = to_tf32(v.z); p[3] = to_tf32(v.w);
            }
            __syncthreads();

            float d[4][4][4];
#pragma unroll
            for (int i = 0; i < 4; i++)
#pragma unroll
                for (int j = 0; j < 4; j++)
#pragma unroll
                    for (int e = 0; e < 4; e++) d[i][j][e] = 0.f;

#pragma unroll
            for (int ks = 0; ks < 8; ks++) {
                const int k0 = ks << 3;
                uint32_t af[4][4], bf[4][2];
#pragma unroll
                for (int mt = 0; mt < 4; mt++) {
                    const float* p = Ap + (m0 + (mt << 4) + g) * ALD + k0 + t;
                    af[mt][0] = __float_as_uint(p[0]);
                    af[mt][1] = __float_as_uint(p[8 * ALD]);
                    af[mt][2] = __float_as_uint(p[4]);
                    af[mt][3] = __float_as_uint(p[8 * ALD + 4]);
                }
#pragma unroll
                for (int nt = 0; nt < 4; nt++) {
                    const float* p = Bp + (n0 + (nt << 3) + g) * ALD + k0 + t;
                    bf[nt][0] = __float_as_uint(p[0]);
                    bf[nt][1] = __float_as_uint(p[4]);
                }
#pragma unroll
                for (int mt = 0; mt < 4; mt++)
#pragma unroll
                    for (int nt = 0; nt < 4; nt++)
                        MMA_TF32(d[mt][nt], af[mt], bf[nt]);
            }

            if (pass == 0) {
                // per-row chunk max -> atomicMax into rowmaxU
#pragma unroll
                for (int mt = 0; mt < 4; mt++)
#pragma unroll
                    for (int half = 0; half < 2; half++) {
                        float mx = -FLT_MAX;
#pragma unroll
                        for (int nt = 0; nt < 4; nt++)
                            mx = fmaxf(mx, fmaxf(d[mt][nt][half * 2],
                                                 d[mt][nt][half * 2 + 1]));
                        mx = fmaxf(mx, __shfl_xor_sync(0xffffffffu, mx, 1));
                        mx = fmaxf(mx, __shfl_xor_sync(0xffffffffu, mx, 2));
                        if (t == 0)
                            atomicMax(&rowmaxU[m0 + (mt << 4) + g + half * 8], fenc(mx));
                    }
            } else {
                // collect candidates within raw band 0.32 (= 0.04 score units)
#pragma unroll
                for (int mt = 0; mt < 4; mt++)
#pragma unroll
                    for (int half = 0; half < 2; half++) {
                        const int row = m0 + (mt << 4) + g + half * 8;
                        const float band = fdec(rowmaxU[row]) - 0.32f;
#pragma unroll
                        for (int nt = 0; nt < 4; nt++)
#pragma unroll
                            for (int e = 0; e < 2; e++) {
                                float v = d[mt][nt][half * 2 + e];
                                if (v >= band) {
                                    int pos = atomicAdd(&cntI[row], 1);
                                    if (pos < 16)
                                        listKs[row * 16 + pos] =
                                            ch * 128 + n0 + (nt << 3) + (t << 1) + e;
                                }
                            }
                    }
            }
        }
    }
    __syncthreads();

    // -------------------- phase 3: exact fixup + softmax + AV ---------------
    float* fb = Bp;   // Bp free now: 8 warps x 1024 floats fallback buffer

    for (int rr = 0; rr < 16; rr++) {
        const int r = w * 16 + rr;
        const int q = q0 + r;
        const float* qrow = qbase + (size_t)r * HD;
        int cnt = cntI[r];
        float a0 = 0.f, a1 = 0.f;

        if (cnt <= 16) {
            // sort candidate list (determinism: atomicAdd order is arbitrary)
            if (lane == 0) {
                for (int a = 1; a < cnt; a++) {
                    int key = listKs[r * 16 + a];
                    int b = a - 1;
                    while (b >= 0 && listKs[r * 16 + b] > key) {
                        listKs[r * 16 + b + 1] = listKs[r * 16 + b];
                        b--;
                    }
                    listKs[r * 16 + b + 1] = key;
                }
            }
            __syncwarp();

            // exact fp32 dots for candidates
            const float qa = qrow[lane], qb = qrow[lane + 32];
            for (int j = 0; j < cnt; j++) {
                const int k = listKs[r * 16 + j];
                const float* krow = kbh + (size_t)k * HD;
                float p = qa * krow[lane] + qb * krow[lane + 32];
#pragma unroll
                for (int o = 16; o > 0; o >>= 1)
                    p += __shfl_xor_sync(0xffffffffu, p, o);
                if (lane == 0) listSs[r * 16 + j] = p * 0.125f;
            }
            __syncwarp();

            float m_ex = -FLT_MAX;
            for (int j = 0; j < cnt; j++) m_ex = fmaxf(m_ex, listSs[r * 16 + j]);
            const float xm = m_ex / 0.001f;
            float Z = 0.f;
            for (int j = 0; j < cnt; j++)
                Z += expf(listSs[r * 16 + j] / 0.001f - xm);

            float m2 = -FLT_MAX;
            for (int j = 0; j < cnt; j++) {
                float att = expf(listSs[r * 16 + j] / 0.001f - xm) / Z;
                if (att >= 0.019f) m2 = fmaxf(m2, listSs[r * 16 + j]);
            }
            // cnt<=16 => Z<=16 => max att >= 1/16 > 0.019 => nsurv >= 1 always
            float wsum = 0.f;
            for (int j = 0; j < cnt; j++) {
                float s = listSs[r * 16 + j];
                float att = expf(s / 0.001f - xm) / Z;
                if (att >= 0.019f) wsum += expf(s - m2);
            }
            for (int j = 0; j < cnt; j++) {
                float s = listSs[r * 16 + j];
                float att = expf(s / 0.001f - xm) / Z;
                if (att >= 0.019f) {
                    float wgt = expf(s - m2) / wsum;
                    const int k = listKs[r * 16 + j];
                    a0 += wgt * vb[(size_t)k * HD + lane];
                    a1 += wgt * vb[(size_t)k * HD + lane + 32];
                }
            }
        } else {
            // RARE overflow: recompute full row exactly (R5 fallback semantics)
            float* frow = fb + w * 1024;
            for (int it = 0; it < 32; it++) {
                int k = it * 32 + lane;
                const float* krow = kbh + (size_t)k * HD;
                float p = 0.f;
#pragma unroll
                for (int dd = 0; dd < 64; dd++) p += qrow[dd] * krow[dd];
                frow[k] = p * 0.125f;
            }
            __syncwarp();
            float me = -FLT_MAX;
            for (int k = lane; k < 1024; k += 32) me = fmaxf(me, frow[k]);
#pragma unroll
            for (int o = 16; o > 0; o >>= 1)
                me = fmaxf(me, __shfl_xor_sync(0xffffffffu, me, o));
            const float xm = me / 0.001f;
            float Z = 0.f;
            for (int k = lane; k < 1024; k += 32)
                Z += expf(frow[k] / 0.001f - xm);
#pragma unroll
            for (int o = 16; o > 0; o >>= 1)
                Z += __shfl_xor_sync(0xffffffffu, Z, o);
            float m2 = -FLT_MAX;
            for (int k = lane; k < 1024; k += 32)
                if (expf(frow[k] / 0.001f - xm) / Z >= 0.019f)
                    m2 = fmaxf(m2, frow[k]);
#pragma unroll
            for (int o = 16; o > 0; o >>= 1)
                m2 = fmaxf(m2, __shfl_xor_sync(0xffffffffu, m2, o));
            const bool any = (m2 > -1e37f);
            float wsum = 0.f;
            if (any) {
                for (int k = lane; k < 1024; k += 32) {
                    float att = expf(frow[k] / 0.001f - xm) / Z;
                    if (att >= 0.019f) wsum += expf(frow[k] - m2);
                }
#pragma unroll
                for (int o = 16; o > 0; o >>= 1)
                    wsum += __shfl_xor_sync(0xffffffffu, wsum, o);
            }
            for (int k = 0; k < 1024; k++) {
                float wgt;
                if (!any) wgt = 1.f / 1024.f;
                else {
                    float att = expf(frow[k] / 0.001f - xm) / Z;
                    wgt = (att >= 0.019f) ? expf(frow[k] - m2) / wsum : 0.f;
                }
                a0 += wgt * vb[(size_t)k * HD + lane];
                a1 += wgt * vb[(size_t)k * HD + lane + 32];
            }
        }

        const int b_ = bh >> 4, h_ = bh & 15;
        float* dst = attn + ((size_t)(b_ * SDIM + q)) * DDIM + h_ * HD;
        dst[lane] = a0;
        dst[lane + 32] = a1;
    }
}

// ---------------------------------------------------------------------------
// tf32 3-pass GEMM (Q/K projections) — unchanged from R5
// ---------------------------------------------------------------------------
#define PLD 36
#define PLANE (128 * PLD)

__global__ __launch_bounds__(256, 1)
void mma_gemm3(const float* __restrict__ A, int lda,
               const float* __restrict__ B, int ldb,
               const float* __restrict__ bias,
               float* __restrict__ C, float scale, int head_layout)
{
    extern __shared__ __align__(16) float smf[];
    float* Ah = smf;
    float* Bh = smf + PLANE;
    float* Al = smf + 2 * PLANE;
    float* Bl = smf + 3 * PLANE;

    const int tid = threadIdx.x;
    const int w = tid >> 5;
    const int lane = tid & 31;
    const int g = lane >> 2;
    const int t = lane & 3;
    const int m0 = (w & 1) << 6;
    const int n0 = (w >> 1) << 5;
    const int row0 = blockIdx.y << 7;
    const int col0 = blockIdx.x << 7;

    float d[4][4][4];
#pragma unroll
    for (int i = 0; i < 4; i++)
#pragma unroll
        for (int j = 0; j < 4; j++)
#pragma unroll
            for (int e = 0; e < 4; e++) d[i][j][e] = 0.f;

    for (int ch = 0; ch < 32; ch++) {
        const int kc = ch << 5;
        __syncthreads();
#pragma unroll
        for (int i = 0; i < 4; i++) {
            int idx = i * 256 + tid;
            int r = idx >> 3, c4 = (idx & 7) << 2;
            float4 va = *(const float4*)(A + (size_t)(row0 + r) * lda + kc + c4);
            float* pa = Ah + r * PLD + c4;
            float hx = to_tf32(va.x), hy = to_tf32(va.y),
                  hz = to_tf32(va.z), hw = to_tf32(va.w);
            pa[0] = hx; pa[1] = hy; pa[2] = hz; pa[3] = hw;
            float* ql = Al + r * PLD + c4;
            ql[0] = to_tf32(va.x - hx); ql[1] = to_tf32(va.y - hy);
            ql[2] = to_tf32(va.z - hz); ql[3] = to_tf32(va.w - hw);
            float4 vb = *(const float4*)(B + (size_t)(col0 + r) * ldb + kc + c4);
            float* pb = Bh + r * PLD + c4;
            hx = to_tf32(vb.x); hy = to_tf32(vb.y);
            hz = to_tf32(vb.z); hw = to_tf32(vb.w);
            pb[0] = hx; pb[1] = hy; pb[2] = hz; pb[3] = hw;
            float* rl = Bl + r * PLD + c4;
            rl[0] = to_tf32(vb.x - hx); rl[1] = to_tf32(vb.y - hy);
            rl[2] = to_tf32(vb.z - hz); rl[3] = to_tf32(vb.w - hw);
        }
        __syncthreads();

#pragma unroll
        for (int ks = 0; ks < 4; ks++) {
            const int k0 = ks << 3;
            uint32_t af[4][4], bf[4][2];
#pragma unroll
            for (int mt = 0; mt < 4; mt++) {
                const float* p = Ah + (m0 + (mt << 4) + g) * PLD + k0 + t;
                af[mt][0] = __float_as_uint(p[0]);
                af[mt][1] = __float_as_uint(p[8 * PLD]);
                af[mt][2] = __float_as_uint(p[4]);
                af[mt][3] = __float_as_uint(p[8 * PLD + 4]);
            }
#pragma unroll
            for (int nt = 0; nt < 4; nt++) {
                const float* p = Bh + (n0 + (nt << 3) + g) * PLD + k0 + t;
                bf[nt][0] = __float_as_uint(p[0]);
                bf[nt][1] = __float_as_uint(p[4]);
            }
#pragma unroll
            for (int mt = 0; mt < 4; mt++)
#pragma unroll
                for (int nt = 0; nt < 4; nt++)
                    MMA_TF32(d[mt][nt], af[mt], bf[nt]);

            uint32_t lf[4][2];
#pragma unroll
            for (int nt = 0; nt < 4; nt++) {
                const float* p = Bl + (n0 + (nt << 3) + g) * PLD + k0 + t;
                lf[nt][0] = __float_as_uint(p[0]);
                lf[nt][1] = __float_as_uint(p[4]);
            }
#pragma unroll
            for (int mt = 0; mt < 4; mt++)
#pragma unroll
                for (int nt = 0; nt < 4; nt++)
                    MMA_TF32(d[mt][nt], af[mt], lf[nt]);
            uint32_t alf[4][4];
#pragma unroll
            for (int mt = 0; mt < 4; mt++) {
                const float* p = Al + (m0 + (mt << 4) + g) * PLD + k0 + t;
                alf[mt][0] = __float_as_uint(p[0]);
                alf[mt][1] = __float_as_uint(p[8 * PLD]);
                alf[mt][2] = __float_as_uint(p[4]);
                alf[mt][3] = __float_as_uint(p[8 * PLD + 4]);
            }
#pragma unroll
            for (int mt = 0; mt < 4; mt++)
#pragma unroll
                for (int nt = 0; nt < 4; nt++)
                    MMA_TF32(d[mt][nt], alf[mt], bf[nt]);
        }
    }

#pragma unroll
    for (int mt = 0; mt < 4; mt++) {
#pragma unroll
        for (int nt = 0; nt < 4; nt++) {
            int c = col0 + n0 + (nt << 3) + (t << 1);
            float b0 = bias ? bias[c] : 0.f;
            float b1 = bias ? bias[c + 1] : 0.f;
#pragma unroll
            for (int half = 0; half < 2; half++) {
                int r = row0 + m0 + (mt << 4) + g + half * 8;
                float2 v;
                v.x = d[mt][nt][half * 2 + 0] * scale + b0;
                v.y = d[mt][nt][half * 2 + 1] * scale + b1;
                if (head_layout) {
                    int b_ = r >> 10, s_ = r & 1023;
                    int h_ = c >> 6, d_ = c & 63;
                    *(float2*)(C + (((size_t)(b_ * NH + h_) * SDIM + s_) << 6) + d_) = v;
                } else {
                    *(float2*)(C + (size_t)r * 1024 + c) = v;
                }
            }
        }
    }
}

// ---------------------------------------------------------------------------
// bf16 3-product GEMM (V/O projections) — unchanged from R5
// ---------------------------------------------------------------------------
#define BPLD 20
#define BPLANE (128 * BPLD)

__device__ __forceinline__ uint32_t pack_bf16(float a, float b) {
    __nv_bfloat162 v = __floats2bfloat162_rn(a, b);
    return *reinterpret_cast<uint32_t*>(&v);
}

__global__ __launch_bounds__(256, 1)
void mma_gemm_bf16(const float* __restrict__ A, int lda,
                   const float* __restrict__ B, int ldb,
                   const float* __restrict__ bias,
                   float* __restrict__ C, float scale, int head_layout)
{
    __shared__ __align__(16) uint32_t Ah[BPLANE];
    __shared__ __align__(16) uint32_t Al[BPLANE];
    __shared__ __align__(16) uint32_t Bh_[BPLANE];
    __shared__ __align__(16) uint32_t Bl[BPLANE];

    const int tid = threadIdx.x;
    const int w = tid >> 5;
    const int lane = tid & 31;
    const int g = lane >> 2;
    const int t = lane & 3;
    const int m0 = (w & 1) << 6;
    const int n0 = (w >> 1) << 5;
    const int row0 = blockIdx.y << 7;
    const int col0 = blockIdx.x << 7;

    float d[4][4][4];
#pragma unroll
    for (int i = 0; i < 4; i++)
#pragma unroll
        for (int j = 0; j < 4; j++)
#pragma unroll
            for (int e = 0; e < 4; e++) d[i][j][e] = 0.f;

    const int s_ = tid & 7;
    const int j0 = (2 * s_) & 7;
    const int phys0 = ((s_ >> 2) << 3) + ((j0 & 3) << 1) + (j0 >> 2);

    for (int ch = 0; ch < 32; ch++) {
        const int kc = ch << 5;
        __syncthreads();
#pragma unroll
        for (int i = 0; i < 4; i++) {
            int idx = i * 256 + tid;
            int r = idx >> 3;
            int wo = r * BPLD + phys0;
            float4 va = *(const float4*)(A + (size_t)(row0 + r) * lda + kc + s_ * 4);
            float hx = __bfloat162float(__float2bfloat16_rn(va.x));
            float hy = __bfloat162float(__float2bfloat16_rn(va.y));
            float hz = __bfloat162float(__float2bfloat16_rn(va.z));
            float hw = __bfloat162float(__float2bfloat16_rn(va.w));
            Ah[wo]     = pack_bf16(hx, hy);
            Ah[wo + 2] = pack_bf16(hz, hw);
            Al[wo]     = pack_bf16(va.x - hx, va.y - hy);
            Al[wo + 2] = pack_bf16(va.z - hz, va.w - hw);
            float4 vb = *(const float4*)(B + (size_t)(col0 + r) * ldb + kc + s_ * 4);
            hx = __bfloat162float(__float2bfloat16_rn(vb.x));
            hy = __bfloat162float(__float2bfloat16_rn(vb.y));
            hz = __bfloat162float(__float2bfloat16_rn(vb.z));
            hw = __bfloat162float(__float2bfloat16_rn(vb.w));
            Bh_[wo]     = pack_bf16(hx, hy);
            Bh_[wo + 2] = pack_bf16(hz, hw);
            Bl[wo]     = pack_bf16(vb.x - hx, vb.y - hy);
            Bl[wo + 2] = pack_bf16(vb.z - hz, vb.w - hw);
        }
        __syncthreads();

#pragma unroll
        for (int ks = 0; ks < 2; ks++) {
            const int kw = (ks << 3) + (t << 1);
            uint2 aH[4][2], aL[4][2], bH[4], bL[4];
#pragma unroll
            for (int mt = 0; mt < 4; mt++) {
                int rw = (m0 + (mt << 4) + g) * BPLD + kw;
                aH[mt][0] = *(const uint2*)&Ah[rw];
                aH[mt][1] = *(const uint2*)&Ah[rw + 8 * BPLD];
                aL[mt][0] = *(const uint2*)&Al[rw];
                aL[mt][1] = *(const uint2*)&Al[rw + 8 * BPLD];
            }
#pragma unroll
            for (int nt = 0; nt < 4; nt++) {
                int rw = (n0 + (nt << 3) + g) * BPLD + kw;
                bH[nt] = *(const uint2*)&Bh_[rw];
                bL[nt] = *(const uint2*)&Bl[rw];
            }
#pragma unroll
            for (int mt = 0; mt < 4; mt++)
#pragma unroll
                for (int nt = 0; nt < 4; nt++) {
                    MMA_BF16(d[mt][nt], aH[mt][0].x, aH[mt][1].x, aH[mt][0].y, aH[mt][1].y,
                             bH[nt].x, bH[nt].y);
                    MMA_BF16(d[mt][nt], aH[mt][0].x, aH[mt][1].x, aH[mt][0].y, aH[mt][1].y,
                             bL[nt].x, bL[nt].y);
                    MMA_BF16(d[mt][nt], aL[mt][0].x, aL[mt][1].x, aL[mt][0].y, aL[mt][1].y,
                             bH[nt].x, bH[nt].y);
                }
        }
    }

#pragma unroll
    for (int mt = 0; mt < 4; mt++) {
#pragma unroll
        for (int nt = 0; nt < 4; nt++) {
            int c = col0 + n0 + (nt << 3) + (t << 1);
            float b0 = bias ? bias[c] : 0.f;
            float b1 = bias ? bias[c + 1] : 0.f;
#pragma unroll
            for (int half = 0; half < 2; half++) {
                int r = row0 + m0 + (mt << 4) + g + half * 8;
                float2 v;
                v.x = d[mt][nt][half * 2 + 0] * scale + b0;
                v.y = d[mt][nt][half * 2 + 1] * scale + b1;
                if (head_layout) {
                    int b_ = r >> 10, s2 = r & 1023;
                    int h_ = c >> 6, d_ = c & 63;
                    *(float2*)(C + (((size_t)(b_ * NH + h_) * SDIM + s2) << 6) + d_) = v;
                } else {
                    *(float2*)(C + (size_t)r * 1024 + c) = v;
                }
            }
        }
    }
}

// ---------------------------------------------------------------------------
// 1024x1024 transpose
// ---------------------------------------------------------------------------
__global__ __launch_bounds__(256)
void transpose_kernel(const float* __restrict__ in, float* __restrict__ out)
{
    __shared__ float tb[32][33];
    const int tx = threadIdx.x, ty = threadIdx.y;
    const int bx = blockIdx.x << 5, by = blockIdx.y << 5;
#pragma unroll
    for (int i = 0; i < 4; i++)
        tb[ty + i * 8][tx] = in[(size_t)(by + ty + i * 8) * 1024 + bx + tx];
    __syncthreads();
#pragma unroll
    for (int i = 0; i < 4; i++)
        out[(size_t)(bx + ty + i * 8) * 1024 + by + tx] = tb[tx][ty + i * 8];
}

// ---------------------------------------------------------------------------
extern "C" void kernel_launch(void* const* d_in, const int* in_sizes, int n_in,
                              void* d_out, int out_size)
{
    const float* Q  = (const float*)d_in[0];
    const float* K  = (const float*)d_in[1];
    const float* V  = (const float*)d_in[2];
    const float* Wq = (const float*)d_in[3];
    const float* bq = (const float*)d_in[4];
    const float* Wk = (const float*)d_in[5];
    const float* bk = (const float*)d_in[6];
    const float* Wv = (const float*)d_in[7];
    const float* bv = (const float*)d_in[8];
    const float* Wo = (const float*)d_in[9];
    const float* bo = (const float*)d_in[10];

    float *qh, *kh, *vh, *attn, *wqT, *wkT, *wvT, *woT;
    cudaGetSymbolAddress((void**)&qh,   g_qh);
    cudaGetSymbolAddress((void**)&kh,   g_kh);
    cudaGetSymbolAddress((void**)&vh,   g_vh);
    cudaGetSymbolAddress((void**)&attn, g_attn);
    cudaGetSymbolAddress((void**)&wqT,  g_wqT);
    cudaGetSymbolAddress((void**)&wkT,  g_wkT);
    cudaGetSymbolAddress((void**)&wvT,  g_wvT);
    cudaGetSymbolAddress((void**)&woT,  g_woT);

    const int SM3 = 4 * PLANE * 4;   // 73728 B
    cudaFuncSetAttribute(mma_gemm3, cudaFuncAttributeMaxDynamicSharedMemorySize, SM3);
    cudaFuncSetAttribute(fused_scores_mask,
                         cudaFuncAttributeMaxDynamicSharedMemorySize, F_SMEM);

    // weight transposes
    dim3 tb(32, 8), tg(32, 32);
    transpose_kernel<<<tg, tb>>>(Wq, wqT);
    transpose_kernel<<<tg, tb>>>(Wk, wkT);
    transpose_kernel<<<tg, tb>>>(Wv, wvT);
    transpose_kernel<<<tg, tb>>>(Wo, woT);

    // Q,K projections: tensor 3xTF32 (mask-critical precision class)
    mma_gemm3<<<dim3(8, 32), 256, SM3>>>(Q, 1024, wqT, 1024, bq, qh, 1.0f, 1);
    mma_gemm3<<<dim3(8, 32), 256, SM3>>>(K, 1024, wkT, 1024, bk, kh, 1.0f, 1);

    // V projection: bf16 3-product
    mma_gemm_bf16<<<dim3(8, 32), 256>>>(V, 1024, wvT, 1024, bv, vh, 1.0f, 1);

    // fused scores + mask + sparse AV (no score materialization)
    fused_scores_mask<<<dim3(8, NBH), 256, F_SMEM>>>(qh, kh, vh, attn);

    // output projection: bf16 3-product
    mma_gemm_bf16<<<dim3(8, 32), 256>>>(attn, 1024, woT, 1024, bo,
                                        (float*)d_out, 1.0f, 0);
}

// round 7
// speedup vs baseline: 1.5684x; 1.1112x over previous
#include <cuda_runtime.h>
#include <cuda_bf16.h>
#include <math.h>
#include <stdint.h>
#include <float.h>

#define SDIM 1024
#define DDIM 1024
#define NH 16
#define HD 64
#define NBH 64
#define MTOT 4096

// ---------------- scratch (__device__ globals; no runtime alloc) ------------
__device__ float g_qh[NBH * SDIM * HD];
__device__ float g_kh[NBH * SDIM * HD];
__device__ float g_vh[NBH * SDIM * HD];
__device__ float g_attn[(size_t)MTOT * DDIM];
__device__ float g_wqT[DDIM * DDIM];
__device__ float g_wkT[DDIM * DDIM];
__device__ float g_wvT[DDIM * DDIM];
__device__ float g_woT[DDIM * DDIM];

// ---------------- helpers ----------------------------------------------------
__device__ __forceinline__ float to_tf32(float x) {
    uint32_t u;
    asm("cvt.rna.tf32.f32 %0, %1;" : "=r"(u) : "f"(x));
    return __uint_as_float(u);
}

#define MMA_TF32(d, a, b) \
    asm volatile("mma.sync.aligned.m16n8k8.row.col.f32.tf32.tf32.f32 " \
                 "{%0,%1,%2,%3}, {%4,%5,%6,%7}, {%8,%9}, {%0,%1,%2,%3};" \
                 : "+f"((d)[0]), "+f"((d)[1]), "+f"((d)[2]), "+f"((d)[3]) \
                 : "r"((a)[0]), "r"((a)[1]), "r"((a)[2]), "r"((a)[3]), \
                   "r"((b)[0]), "r"((b)[1]))

#define MMA_BF16(d, a0, a1, a2, a3, b0, b1) \
    asm volatile("mma.sync.aligned.m16n8k16.row.col.f32.bf16.bf16.f32 " \
                 "{%0,%1,%2,%3}, {%4,%5,%6,%7}, {%8,%9}, {%0,%1,%2,%3};" \
                 : "+f"((d)[0]), "+f"((d)[1]), "+f"((d)[2]), "+f"((d)[3]) \
                 : "r"(a0), "r"(a1), "r"(a2), "r"(a3), "r"(b0), "r"(b1))

// monotone float<->uint encoding for atomicMax on floats
__device__ __forceinline__ unsigned fenc(float f) {
    unsigned u = __float_as_uint(f);
    return (u & 0x80000000u) ? ~u : (u | 0x80000000u);
}
__device__ __forceinline__ float fdec(unsigned u) {
    unsigned v = (u & 0x80000000u) ? (u & 0x7FFFFFFFu) : ~u;
    return __uint_as_float(v);
}

// ---------------------------------------------------------------------------
// FUSED scores + mask + sparse AV — SINGLE PASS.
// Candidates collected against the RUNNING row max (atomicMax) — a superset
// of the final-max band (running <= final). Phase 3 filters by exact fp32
// scores, so extras are harmless (contribute e^-40 to Z, never survive).
// ---------------------------------------------------------------------------
#define ALD 68
#define CAP 32
#define F_SMEM (34816 + 34816 + 512 + 512 + 16384 + 16384)   // 103424 B

__global__ __launch_bounds__(256, 2)
void fused_scores_mask(const float* __restrict__ qh, const float* __restrict__ kh,
                       const float* __restrict__ vh, float* __restrict__ attn)
{
    extern __shared__ __align__(16) char fsm[];
    float*    Ap      = (float*)fsm;                   // 128 x 68 tf32 q
    float*    Bp      = (float*)(fsm + 34816);         // 128 x 68 tf32 k chunk
    unsigned* rowmaxU = (unsigned*)(fsm + 69632);      // 128
    int*      cntI    = (int*)(fsm + 70144);           // 128
    int*      listKs  = (int*)(fsm + 70656);           // 128 x 32
    float*    listSs  = (float*)(fsm + 87040);         // 128 x 32

    const int tid = threadIdx.x;
    const int w = tid >> 5;
    const int lane = tid & 31;
    const int g = lane >> 2;
    const int t = lane & 3;
    const int m0 = (w & 1) << 6;
    const int n0 = (w >> 1) << 5;
    const int bh = blockIdx.y;
    const int q0 = blockIdx.x << 7;

    const float* qbase = qh + ((size_t)bh * SDIM + q0) * HD;
    const float* kbh   = kh + (size_t)bh * SDIM * HD;
    const float* vb    = vh + (size_t)bh * SDIM * HD;

    if (tid < 128) { rowmaxU[tid] = 0u; cntI[tid] = 0; }

    // load q tile as tf32 (1-pass precision — exact fixup absorbs noise)
#pragma unroll
    for (int i = 0; i < 8; i++) {
        int idx = i * 256 + tid;              // 2048 float4s
        int r = idx >> 4, c4 = (idx & 15) << 2;
        float4 v = *(const float4*)(qbase + (size_t)r * HD + c4);
        float* p = Ap + r * ALD + c4;
        p[0] = to_tf32(v.x); p[1] = to_tf32(v.y);
        p[2] = to_tf32(v.z); p[3] = to_tf32(v.w);
    }

    for (int ch = 0; ch < 8; ch++) {
        __syncthreads();   // Bp free (prev collect done; first iter: init done)
#pragma unroll
        for (int i = 0; i < 8; i++) {
            int idx = i * 256 + tid;
            int r = idx >> 4, c4 = (idx & 15) << 2;
            float4 v = *(const float4*)(kbh + (size_t)(ch * 128 + r) * HD + c4);
            float* p = Bp + r * ALD + c4;
            p[0] = to_tf32(v.x); p[1] = to_tf32(v.y);
            p[2] = to_tf32(v.z); p[3] = to_tf32(v.w);
        }
        __syncthreads();

        float d[4][4][4];
#pragma unroll
        for (int i = 0; i < 4; i++)
#pragma unroll
            for (int j = 0; j < 4; j++)
#pragma unroll
                for (int e = 0; e < 4; e++) d[i][j][e] = 0.f;

#pragma unroll
        for (int ks = 0; ks < 8; ks++) {
            const int k0 = ks << 3;
            uint32_t af[4][4], bf[4][2];
#pragma unroll
            for (int mt = 0; mt < 4; mt++) {
                const float* p = Ap + (m0 + (mt << 4) + g) * ALD + k0 + t;
                af[mt][0] = __float_as_uint(p[0]);
                af[mt][1] = __float_as_uint(p[8 * ALD]);
                af[mt][2] = __float_as_uint(p[4]);
                af[mt][3] = __float_as_uint(p[8 * ALD + 4]);
            }
#pragma unroll
            for (int nt = 0; nt < 4; nt++) {
                const float* p = Bp + (n0 + (nt << 3) + g) * ALD + k0 + t;
                bf[nt][0] = __float_as_uint(p[0]);
                bf[nt][1] = __float_as_uint(p[4]);
            }
#pragma unroll
            for (int mt = 0; mt < 4; mt++)
#pragma unroll
                for (int nt = 0; nt < 4; nt++)
                    MMA_TF32(d[mt][nt], af[mt], bf[nt]);
        }

        // update running row max
#pragma unroll
        for (int mt = 0; mt < 4; mt++)
#pragma unroll
            for (int half = 0; half < 2; half++) {
                float mx = -FLT_MAX;
#pragma unroll
                for (int nt = 0; nt < 4; nt++)
                    mx = fmaxf(mx, fmaxf(d[mt][nt][half * 2],
                                         d[mt][nt][half * 2 + 1]));
                mx = fmaxf(mx, __shfl_xor_sync(0xffffffffu, mx, 1));
                mx = fmaxf(mx, __shfl_xor_sync(0xffffffffu, mx, 2));
                if (t == 0)
                    atomicMax(&rowmaxU[m0 + (mt << 4) + g + half * 8], fenc(mx));
            }
        __syncthreads();   // running max (incl. this chunk, all warps) visible

        // collect candidates vs running max (superset of final band)
#pragma unroll
        for (int mt = 0; mt < 4; mt++)
#pragma unroll
            for (int half = 0; half < 2; half++) {
                const int row = m0 + (mt << 4) + g + half * 8;
                const float band = fdec(rowmaxU[row]) - 0.32f;
#pragma unroll
                for (int nt = 0; nt < 4; nt++)
#pragma unroll
                    for (int e = 0; e < 2; e++) {
                        float v = d[mt][nt][half * 2 + e];
                        if (v >= band) {
                            int pos = atomicAdd(&cntI[row], 1);
                            if (pos < CAP)
                                listKs[row * CAP + pos] =
                                    ch * 128 + n0 + (nt << 3) + (t << 1) + e;
                        }
                    }
            }
    }
    __syncthreads();

    // -------------------- phase 3: exact fixup + softmax + AV ---------------
    float* fb = Bp;   // Bp free now: 8 warps x 1024 floats fallback buffer

    for (int rr = 0; rr < 16; rr++) {
        const int r = w * 16 + rr;
        const int q = q0 + r;
        const float* qrow = qbase + (size_t)r * HD;
        int cnt = cntI[r];
        float a0 = 0.f, a1 = 0.f;

        if (cnt <= CAP) {
            // sort candidate list (determinism: atomicAdd order is arbitrary)
            if (lane == 0) {
                for (int a = 1; a < cnt; a++) {
                    int key = listKs[r * CAP + a];
                    int b = a - 1;
                    while (b >= 0 && listKs[r * CAP + b] > key) {
                        listKs[r * CAP + b + 1] = listKs[r * CAP + b];
                        b--;
                    }
                    listKs[r * CAP + b + 1] = key;
                }
            }
            __syncwarp();

            // exact fp32 dots for candidates
            const float qa = qrow[lane], qb = qrow[lane + 32];
            for (int j = 0; j < cnt; j++) {
                const int k = listKs[r * CAP + j];
                const float* krow = kbh + (size_t)k * HD;
                float p = qa * krow[lane] + qb * krow[lane + 32];
#pragma unroll
                for (int o = 16; o > 0; o >>= 1)
                    p += __shfl_xor_sync(0xffffffffu, p, o);
                if (lane == 0) listSs[r * CAP + j] = p * 0.125f;
            }
            __syncwarp();

            float m_ex = -FLT_MAX;
            for (int j = 0; j < cnt; j++) m_ex = fmaxf(m_ex, listSs[r * CAP + j]);
            const float xm = m_ex / 0.001f;
            float Z = 0.f;
            for (int j = 0; j < cnt; j++)
                Z += expf(listSs[r * CAP + j] / 0.001f - xm);

            float m2 = -FLT_MAX;
            for (int j = 0; j < cnt; j++) {
                float att = expf(listSs[r * CAP + j] / 0.001f - xm) / Z;
                if (att >= 0.019f) m2 = fmaxf(m2, listSs[r * CAP + j]);
            }
            // cnt<=32 => Z<=32 => max att >= 1/32 > 0.019 => nsurv >= 1 always
            float wsum = 0.f;
            for (int j = 0; j < cnt; j++) {
                float s = listSs[r * CAP + j];
                float att = expf(s / 0.001f - xm) / Z;
                if (att >= 0.019f) wsum += expf(s - m2);
            }
            for (int j = 0; j < cnt; j++) {
                float s = listSs[r * CAP + j];
                float att = expf(s / 0.001f - xm) / Z;
                if (att >= 0.019f) {
                    float wgt = expf(s - m2) / wsum;
                    const int k = listKs[r * CAP + j];
                    a0 += wgt * vb[(size_t)k * HD + lane];
                    a1 += wgt * vb[(size_t)k * HD + lane + 32];
                }
            }
        } else {
            // RARE overflow: recompute full row exactly
            float* frow = fb + w * 1024;
            for (int it = 0; it < 32; it++) {
                int k = it * 32 + lane;
                const float* krow = kbh + (size_t)k * HD;
                float p = 0.f;
#pragma unroll
                for (int dd = 0; dd < 64; dd++) p += qrow[dd] * krow[dd];
                frow[k] = p * 0.125f;
            }
            __syncwarp();
            float me = -FLT_MAX;
            for (int k = lane; k < 1024; k += 32) me = fmaxf(me, frow[k]);
#pragma unroll
            for (int o = 16; o > 0; o >>= 1)
                me = fmaxf(me, __shfl_xor_sync(0xffffffffu, me, o));
            const float xm = me / 0.001f;
            float Z = 0.f;
            for (int k = lane; k < 1024; k += 32)
                Z += expf(frow[k] / 0.001f - xm);
#pragma unroll
            for (int o = 16; o > 0; o >>= 1)
                Z += __shfl_xor_sync(0xffffffffu, Z, o);
            float m2 = -FLT_MAX;
            for (int k = lane; k < 1024; k += 32)
                if (expf(frow[k] / 0.001f - xm) / Z >= 0.019f)
                    m2 = fmaxf(m2, frow[k]);
#pragma unroll
            for (int o = 16; o > 0; o >>= 1)
                m2 = fmaxf(m2, __shfl_xor_sync(0xffffffffu, m2, o));
            const bool any = (m2 > -1e37f);
            float wsum = 0.f;
            if (any) {
                for (int k = lane; k < 1024; k += 32) {
                    float att = expf(frow[k] / 0.001f - xm) / Z;
                    if (att >= 0.019f) wsum += expf(frow[k] - m2);
                }
#pragma unroll
                for (int o = 16; o > 0; o >>= 1)
                    wsum += __shfl_xor_sync(0xffffffffu, wsum, o);
            }
            for (int k = 0; k < 1024; k++) {
                float wgt;
                if (!any) wgt = 1.f / 1024.f;
                else {
                    float att = expf(frow[k] / 0.001f - xm) / Z;
                    wgt = (att >= 0.019f) ? expf(frow[k] - m2) / wsum : 0.f;
                }
                a0 += wgt * vb[(size_t)k * HD + lane];
                a1 += wgt * vb[(size_t)k * HD + lane + 32];
            }
        }

        const int b_ = bh >> 4, h_ = bh & 15;
        float* dst = attn + ((size_t)(b_ * SDIM + q)) * DDIM + h_ * HD;
        dst[lane] = a0;
        dst[lane + 32] = a1;
    }
}

// ---------------------------------------------------------------------------
// tf32 3-pass GEMM (Q & K projections in one launch, z selects), software-
// pipelined: register-staged global prefetch + double-buffered smem, one
// __syncthreads per chunk.
// ---------------------------------------------------------------------------
#define PLD 36
#define PLANE (128 * PLD)
#define G3_SMEM (2 * 4 * PLANE * 4)   // 147456 B

__global__ __launch_bounds__(256, 1)
void mma_gemm3(const float* __restrict__ A0, const float* __restrict__ W0,
               const float* __restrict__ b0, float* __restrict__ C0,
               const float* __restrict__ A1, const float* __restrict__ W1,
               const float* __restrict__ b1, float* __restrict__ C1)
{
    extern __shared__ __align__(16) float smf[];
    const float* A    = blockIdx.z ? A1 : A0;
    const float* B    = blockIdx.z ? W1 : W0;
    const float* bias = blockIdx.z ? b1 : b0;
    float* C          = blockIdx.z ? C1 : C0;

    const int tid = threadIdx.x;
    const int w = tid >> 5;
    const int lane = tid & 31;
    const int g = lane >> 2;
    const int t = lane & 3;
    const int m0 = (w & 1) << 6;
    const int n0 = (w >> 1) << 5;
    const int row0 = blockIdx.y << 7;
    const int col0 = blockIdx.x << 7;

    float d[4][4][4];
#pragma unroll
    for (int i = 0; i < 4; i++)
#pragma unroll
        for (int j = 0; j < 4; j++)
#pragma unroll
            for (int e = 0; e < 4; e++) d[i][j][e] = 0.f;

    float4 pa[4], pb[4];
#pragma unroll
    for (int i = 0; i < 4; i++) {
        int idx = i * 256 + tid;
        int r = idx >> 3, c4 = (idx & 7) << 2;
        pa[i] = *(const float4*)(A + (size_t)(row0 + r) * 1024 + c4);
        pb[i] = *(const float4*)(B + (size_t)(col0 + r) * 1024 + c4);
    }

    for (int ch = 0; ch < 32; ch++) {
        const int s = ch & 1;
        float* Ah = smf + s * 4 * PLANE;
        float* Bh = Ah + PLANE;
        float* Al = Ah + 2 * PLANE;
        float* Bl = Ah + 3 * PLANE;

        // split + store staged chunk
#pragma unroll
        for (int i = 0; i < 4; i++) {
            int idx = i * 256 + tid;
            int r = idx >> 3, c4 = (idx & 7) << 2;
            float4 va = pa[i];
            float* p = Ah + r * PLD + c4;
            float hx = to_tf32(va.x), hy = to_tf32(va.y),
                  hz = to_tf32(va.z), hw = to_tf32(va.w);
            p[0] = hx; p[1] = hy; p[2] = hz; p[3] = hw;
            float* ql = Al + r * PLD + c4;
            ql[0] = to_tf32(va.x - hx); ql[1] = to_tf32(va.y - hy);
            ql[2] = to_tf32(va.z - hz); ql[3] = to_tf32(va.w - hw);
            float4 vbv = pb[i];
            float* q2 = Bh + r * PLD + c4;
            hx = to_tf32(vbv.x); hy = to_tf32(vbv.y);
            hz = to_tf32(vbv.z); hw = to_tf32(vbv.w);
            q2[0] = hx; q2[1] = hy; q2[2] = hz; q2[3] = hw;
            float* rl = Bl + r * PLD + c4;
            rl[0] = to_tf32(vbv.x - hx); rl[1] = to_tf32(vbv.y - hy);
            rl[2] = to_tf32(vbv.z - hz); rl[3] = to_tf32(vbv.w - hw);
        }
        __syncthreads();

        // prefetch next chunk while mma runs
        if (ch < 31) {
            const int kc = (ch + 1) << 5;
#pragma unroll
            for (int i = 0; i < 4; i++) {
                int idx = i * 256 + tid;
                int r = idx >> 3, c4 = (idx & 7) << 2;
                pa[i] = *(const float4*)(A + (size_t)(row0 + r) * 1024 + kc + c4);
                pb[i] = *(const float4*)(B + (size_t)(col0 + r) * 1024 + kc + c4);
            }
        }

#pragma unroll
        for (int ks = 0; ks < 4; ks++) {
            const int k0 = ks << 3;
            uint32_t af[4][4], bf[4][2];
#pragma unroll
            for (int mt = 0; mt < 4; mt++) {
                const float* p = Ah + (m0 + (mt << 4) + g) * PLD + k0 + t;
                af[mt][0] = __float_as_uint(p[0]);
                af[mt][1] = __float_as_uint(p[8 * PLD]);
                af[mt][2] = __float_as_uint(p[4]);
                af[mt][3] = __float_as_uint(p[8 * PLD + 4]);
            }
#pragma unroll
            for (int nt = 0; nt < 4; nt++) {
                const float* p = Bh + (n0 + (nt << 3) + g) * PLD + k0 + t;
                bf[nt][0] = __float_as_uint(p[0]);
                bf[nt][1] = __float_as_uint(p[4]);
            }
#pragma unroll
            for (int mt = 0; mt < 4; mt++)
#pragma unroll
                for (int nt = 0; nt < 4; nt++)
                    MMA_TF32(d[mt][nt], af[mt], bf[nt]);

            uint32_t lf[4][2];
#pragma unroll
            for (int nt = 0; nt < 4; nt++) {
                const float* p = Bl + (n0 + (nt << 3) + g) * PLD + k0 + t;
                lf[nt][0] = __float_as_uint(p[0]);
                lf[nt][1] = __float_as_uint(p[4]);
            }
#pragma unroll
            for (int mt = 0; mt < 4; mt++)
#pragma unroll
                for (int nt = 0; nt < 4; nt++)
                    MMA_TF32(d[mt][nt], af[mt], lf[nt]);
            uint32_t alf[4][4];
#pragma unroll
            for (int mt = 0; mt < 4; mt++) {
                const float* p = Al + (m0 + (mt << 4) + g) * PLD + k0 + t;
                alf[mt][0] = __float_as_uint(p[0]);
                alf[mt][1] = __float_as_uint(p[8 * PLD]);
                alf[mt][2] = __float_as_uint(p[4]);
                alf[mt][3] = __float_as_uint(p[8 * PLD + 4]);
            }
#pragma unroll
            for (int mt = 0; mt < 4; mt++)
#pragma unroll
                for (int nt = 0; nt < 4; nt++)
                    MMA_TF32(d[mt][nt], alf[mt], bf[nt]);
        }
    }

#pragma unroll
    for (int mt = 0; mt < 4; mt++) {
#pragma unroll
        for (int nt = 0; nt < 4; nt++) {
            int c = col0 + n0 + (nt << 3) + (t << 1);
            float b0v = bias[c];
            float b1v = bias[c + 1];
#pragma unroll
            for (int half = 0; half < 2; half++) {
                int r = row0 + m0 + (mt << 4) + g + half * 8;
                float2 v;
                v.x = d[mt][nt][half * 2 + 0] + b0v;
                v.y = d[mt][nt][half * 2 + 1] + b1v;
                int b_ = r >> 10, s_ = r & 1023;
                int h_ = c >> 6, d_ = c & 63;
                *(float2*)(C + (((size_t)(b_ * NH + h_) * SDIM + s_) << 6) + d_) = v;
            }
        }
    }
}

// ---------------------------------------------------------------------------
// bf16 3-product GEMM (V/O) — software-pipelined double buffer.
// ---------------------------------------------------------------------------
#define BPLD 20
#define BPLANE (128 * BPLD)
#define GB_SMEM (2 * 4 * BPLANE * 4)   // 81920 B

__device__ __forceinline__ uint32_t pack_bf16(float a, float b) {
    __nv_bfloat162 v = __floats2bfloat162_rn(a, b);
    return *reinterpret_cast<uint32_t*>(&v);
}

__global__ __launch_bounds__(256, 1)
void mma_gemm_bf16(const float* __restrict__ A, int lda,
                   const float* __restrict__ B, int ldb,
                   const float* __restrict__ bias,
                   float* __restrict__ C, int head_layout)
{
    extern __shared__ __align__(16) uint32_t smu[];

    const int tid = threadIdx.x;
    const int w = tid >> 5;
    const int lane = tid & 31;
    const int g = lane >> 2;
    const int t = lane & 3;
    const int m0 = (w & 1) << 6;
    const int n0 = (w >> 1) << 5;
    const int row0 = blockIdx.y << 7;
    const int col0 = blockIdx.x << 7;

    float d[4][4][4];
#pragma unroll
    for (int i = 0; i < 4; i++)
#pragma unroll
        for (int j = 0; j < 4; j++)
#pragma unroll
            for (int e = 0; e < 4; e++) d[i][j][e] = 0.f;

    const int s_ = tid & 7;
    const int j0 = (2 * s_) & 7;
    const int phys0 = ((s_ >> 2) << 3) + ((j0 & 3) << 1) + (j0 >> 2);

    float4 pa[4], pb[4];
#pragma unroll
    for (int i = 0; i < 4; i++) {
        int idx = i * 256 + tid;
        int r = idx >> 3;
        pa[i] = *(const float4*)(A + (size_t)(row0 + r) * lda + s_ * 4);
        pb[i] = *(const float4*)(B + (size_t)(col0 + r) * ldb + s_ * 4);
    }

    for (int ch = 0; ch < 32; ch++) {
        const int sb = ch & 1;
        uint32_t* Ah  = smu + sb * 4 * BPLANE;
        uint32_t* Al  = Ah + BPLANE;
        uint32_t* Bh_ = Ah + 2 * BPLANE;
        uint32_t* Bl  = Ah + 3 * BPLANE;

#pragma unroll
        for (int i = 0; i < 4; i++) {
            int idx = i * 256 + tid;
            int r = idx >> 3;
            int wo = r * BPLD + phys0;
            float4 va = pa[i];
            float hx = __bfloat162float(__float2bfloat16_rn(va.x));
            float hy = __bfloat162float(__float2bfloat16_rn(va.y));
            float hz = __bfloat162float(__float2bfloat16_rn(va.z));
            float hw = __bfloat162float(__float2bfloat16_rn(va.w));
            Ah[wo]     = pack_bf16(hx, hy);
            Ah[wo + 2] = pack_bf16(hz, hw);
            Al[wo]     = pack_bf16(va.x - hx, va.y - hy);
            Al[wo + 2] = pack_bf16(va.z - hz, va.w - hw);
            float4 vbv = pb[i];
            hx = __bfloat162float(__float2bfloat16_rn(vbv.x));
            hy = __bfloat162float(__float2bfloat16_rn(vbv.y));
            hz = __bfloat162float(__float2bfloat16_rn(vbv.z));
            hw = __bfloat162float(__float2bfloat16_rn(vbv.w));
            Bh_[wo]     = pack_bf16(hx, hy);
            Bh_[wo + 2] = pack_bf16(hz, hw);
            Bl[wo]     = pack_bf16(vbv.x - hx, vbv.y - hy);
            Bl[wo + 2] = pack_bf16(vbv.z - hz, vbv.w - hw);
        }
        __syncthreads();

        if (ch < 31) {
            const int kc = (ch + 1) << 5;
#pragma unroll
            for (int i = 0; i < 4; i++) {
                int idx = i * 256 + tid;
                int r = idx >> 3;
                pa[i] = *(const float4*)(A + (size_t)(row0 + r) * lda + kc + s_ * 4);
                pb[i] = *(const float4*)(B + (size_t)(col0 + r) * ldb + kc + s_ * 4);
            }
        }

#pragma unroll
        for (int ks = 0; ks < 2; ks++) {
            const int kw = (ks << 3) + (t << 1);
            uint2 aH[4][2], aL[4][2], bH[4], bL[4];
#pragma unroll
            for (int mt = 0; mt < 4; mt++) {
                int rw = (m0 + (mt << 4) + g) * BPLD + kw;
                aH[mt][0] = *(const uint2*)&Ah[rw];
                aH[mt][1] = *(const uint2*)&Ah[rw + 8 * BPLD];
                aL[mt][0] = *(const uint2*)&Al[rw];
                aL[mt][1] = *(const uint2*)&Al[rw + 8 * BPLD];
            }
#pragma unroll
            for (int nt = 0; nt < 4; nt++) {
                int rw = (n0 + (nt << 3) + g) * BPLD + kw;
                bH[nt] = *(const uint2*)&Bh_[rw];
                bL[nt] = *(const uint2*)&Bl[rw];
            }
#pragma unroll
            for (int mt = 0; mt < 4; mt++)
#pragma unroll
                for (int nt = 0; nt < 4; nt++) {
                    MMA_BF16(d[mt][nt], aH[mt][0].x, aH[mt][1].x, aH[mt][0].y, aH[mt][1].y,
                             bH[nt].x, bH[nt].y);
                    MMA_BF16(d[mt][nt], aH[mt][0].x, aH[mt][1].x, aH[mt][0].y, aH[mt][1].y,
                             bL[nt].x, bL[nt].y);
                    MMA_BF16(d[mt][nt], aL[mt][0].x, aL[mt][1].x, aL[mt][0].y, aL[mt][1].y,
                             bH[nt].x, bH[nt].y);
                }
        }
    }

#pragma unroll
    for (int mt = 0; mt < 4; mt++) {
#pragma unroll
        for (int nt = 0; nt < 4; nt++) {
            int c = col0 + n0 + (nt << 3) + (t << 1);
            float b0 = bias[c];
            float b1 = bias[c + 1];
#pragma unroll
            for (int half = 0; half < 2; half++) {
                int r = row0 + m0 + (mt << 4) + g + half * 8;
                float2 v;
                v.x = d[mt][nt][half * 2 + 0] + b0;
                v.y = d[mt][nt][half * 2 + 1] + b1;
                if (head_layout) {
                    int b_ = r >> 10, s2 = r & 1023;
                    int h_ = c >> 6, d_ = c & 63;
                    *(float2*)(C + (((size_t)(b_ * NH + h_) * SDIM + s2) << 6) + d_) = v;
                } else {
                    *(float2*)(C + (size_t)r * 1024 + c) = v;
                }
            }
        }
    }
}

// ---------------------------------------------------------------------------
// 4x 1024x1024 transpose in one launch (z selects pair)
// ---------------------------------------------------------------------------
__global__ __launch_bounds__(256)
void transpose4_kernel(const float* __restrict__ i0, float* __restrict__ o0,
                       const float* __restrict__ i1, float* __restrict__ o1,
                       const float* __restrict__ i2, float* __restrict__ o2,
                       const float* __restrict__ i3, float* __restrict__ o3)
{
    __shared__ float tb[32][33];
    const float* in = (blockIdx.z == 0) ? i0 : (blockIdx.z == 1) ? i1
                    : (blockIdx.z == 2) ? i2 : i3;
    float* out      = (blockIdx.z == 0) ? o0 : (blockIdx.z == 1) ? o1
                    : (blockIdx.z == 2) ? o2 : o3;
    const int tx = threadIdx.x, ty = threadIdx.y;
    const int bx = blockIdx.x << 5, by = blockIdx.y << 5;
#pragma unroll
    for (int i = 0; i < 4; i++)
        tb[ty + i * 8][tx] = in[(size_t)(by + ty + i * 8) * 1024 + bx + tx];
    __syncthreads();
#pragma unroll
    for (int i = 0; i < 4; i++)
        out[(size_t)(bx + ty + i * 8) * 1024 + by + tx] = tb[tx][ty + i * 8];
}

// ---------------------------------------------------------------------------
extern "C" void kernel_launch(void* const* d_in, const int* in_sizes, int n_in,
                              void* d_out, int out_size)
{
    const float* Q  = (const float*)d_in[0];
    const float* K  = (const float*)d_in[1];
    const float* V  = (const float*)d_in[2];
    const float* Wq = (const float*)d_in[3];
    const float* bq = (const float*)d_in[4];
    const float* Wk = (const float*)d_in[5];
    const float* bk = (const float*)d_in[6];
    const float* Wv = (const float*)d_in[7];
    const float* bv = (const float*)d_in[8];
    const float* Wo = (const float*)d_in[9];
    const float* bo = (const float*)d_in[10];

    float *qh, *kh, *vh, *attn, *wqT, *wkT, *wvT, *woT;
    cudaGetSymbolAddress((void**)&qh,   g_qh);
    cudaGetSymbolAddress((void**)&kh,   g_kh);
    cudaGetSymbolAddress((void**)&vh,   g_vh);
    cudaGetSymbolAddress((void**)&attn, g_attn);
    cudaGetSymbolAddress((void**)&wqT,  g_wqT);
    cudaGetSymbolAddress((void**)&wkT,  g_wkT);
    cudaGetSymbolAddress((void**)&wvT,  g_wvT);
    cudaGetSymbolAddress((void**)&woT,  g_woT);

    cudaFuncSetAttribute(mma_gemm3, cudaFuncAttributeMaxDynamicSharedMemorySize, G3_SMEM);
    cudaFuncSetAttribute(mma_gemm_bf16, cudaFuncAttributeMaxDynamicSharedMemorySize, GB_SMEM);
    cudaFuncSetAttribute(fused_scores_mask,
                         cudaFuncAttributeMaxDynamicSharedMemorySize, F_SMEM);

    // all 4 weight transposes in one launch
    transpose4_kernel<<<dim3(32, 32, 4), dim3(32, 8)>>>(Wq, wqT, Wk, wkT,
                                                        Wv, wvT, Wo, woT);

    // Q + K projections: one pipelined tf32-3 launch (z=2)
    mma_gemm3<<<dim3(8, 32, 2), 256, G3_SMEM>>>(Q, wqT, bq, qh,
                                                K, wkT, bk, kh);

    // V projection: pipelined bf16-3
    mma_gemm_bf16<<<dim3(8, 32), 256, GB_SMEM>>>(V, 1024, wvT, 1024, bv, vh, 1);

    // fused scores + mask + sparse AV (single pass)
    fused_scores_mask<<<dim3(8, NBH), 256, F_SMEM>>>(qh, kh, vh, attn);

    // output projection: pipelined bf16-3
    mma_gemm_bf16<<<dim3(8, 32), 256, GB_SMEM>>>(attn, 1024, woT, 1024, bo,
                                                 (float*)d_out, 0);
}